// round 1
// baseline (speedup 1.0000x reference)
#include <cuda_runtime.h>
#include <cstdint>

// Problem constants
#define B_   8
#define S_   1024
#define D_   1024
#define H_   16
#define HD_  64
#define MROWS (B_ * S_)      // 8192

// ---------------- scratch (static device globals; no allocation allowed) ----
__device__ float g_Q[(size_t)MROWS * D_];
__device__ float g_K[(size_t)MROWS * D_];
__device__ float g_V[(size_t)MROWS * D_];
__device__ float g_C[(size_t)MROWS * D_];   // attention context

// ---------------- SGEMM: C[m,n] = sum_k A[m,k] * W[n,k] + bias[n] -----------
// A: [M,K] row-major, W: [N,K] row-major (i.e. computes A @ W^T + b)
#define BM 128
#define BN 128
#define BK 8

__global__ __launch_bounds__(256, 2)
void sgemm_atb_bias(const float* __restrict__ A, const float* __restrict__ W,
                    const float* __restrict__ bias, float* __restrict__ C,
                    int M, int N, int K) {
    __shared__ float As[BK][BM];
    __shared__ float Ws[BK][BN];

    const int tid = threadIdx.x;
    const int tx = tid & 15;          // 0..15 -> 8 cols each
    const int ty = tid >> 4;          // 0..15 -> 8 rows each
    const int m0 = blockIdx.y * BM;
    const int n0 = blockIdx.x * BN;

    const int lrow = tid >> 1;        // 0..127
    const int lk   = (tid & 1) * 4;   // 0 or 4

    const float* Aptr = A + (size_t)(m0 + lrow) * K + lk;
    const float* Wptr = W + (size_t)(n0 + lrow) * K + lk;

    float acc[8][8];
    #pragma unroll
    for (int i = 0; i < 8; i++)
        #pragma unroll
        for (int j = 0; j < 8; j++) acc[i][j] = 0.f;

    for (int k0 = 0; k0 < K; k0 += BK) {
        float4 av = *(const float4*)(Aptr + k0);
        float4 wv = *(const float4*)(Wptr + k0);
        As[lk + 0][lrow] = av.x; As[lk + 1][lrow] = av.y;
        As[lk + 2][lrow] = av.z; As[lk + 3][lrow] = av.w;
        Ws[lk + 0][lrow] = wv.x; Ws[lk + 1][lrow] = wv.y;
        Ws[lk + 2][lrow] = wv.z; Ws[lk + 3][lrow] = wv.w;
        __syncthreads();

        #pragma unroll
        for (int kk = 0; kk < BK; kk++) {
            float a[8], w[8];
            float4 a0 = *(const float4*)&As[kk][ty * 8];
            float4 a1 = *(const float4*)&As[kk][ty * 8 + 4];
            float4 w0 = *(const float4*)&Ws[kk][tx * 8];
            float4 w1 = *(const float4*)&Ws[kk][tx * 8 + 4];
            a[0]=a0.x; a[1]=a0.y; a[2]=a0.z; a[3]=a0.w;
            a[4]=a1.x; a[5]=a1.y; a[6]=a1.z; a[7]=a1.w;
            w[0]=w0.x; w[1]=w0.y; w[2]=w0.z; w[3]=w0.w;
            w[4]=w1.x; w[5]=w1.y; w[6]=w1.z; w[7]=w1.w;
            #pragma unroll
            for (int i = 0; i < 8; i++)
                #pragma unroll
                for (int j = 0; j < 8; j++) acc[i][j] += a[i] * w[j];
        }
        __syncthreads();
    }

    // epilogue with bias
    float bcol[8];
    #pragma unroll
    for (int j = 0; j < 8; j++) bcol[j] = bias[n0 + tx * 8 + j];

    #pragma unroll
    for (int i = 0; i < 8; i++) {
        float* crow = C + (size_t)(m0 + ty * 8 + i) * N + n0 + tx * 8;
        float4 v0 = make_float4(acc[i][0] + bcol[0], acc[i][1] + bcol[1],
                                acc[i][2] + bcol[2], acc[i][3] + bcol[3]);
        float4 v1 = make_float4(acc[i][4] + bcol[4], acc[i][5] + bcol[5],
                                acc[i][6] + bcol[6], acc[i][7] + bcol[7]);
        *(float4*)(crow)     = v0;
        *(float4*)(crow + 4) = v1;
    }
}

// ---------------- fused attention: scores + softmax + attn out + ctx --------
// One CTA handles (b, h, 32 query rows). Full score tile kept in smem.
#define QR   32
#define SKV  32
#define SC_STRIDE 1032   // 1024 + 8 pad -> conflict-free row offsets

__global__ __launch_bounds__(256, 1)
void attn_kernel(const float* __restrict__ Q, const float* __restrict__ K,
                 const float* __restrict__ V, float* __restrict__ attn,
                 float* __restrict__ ctx) {
    extern __shared__ float sm[];
    float* sc = sm;                               // [QR][SC_STRIDE]
    float* qs = sm + (size_t)QR * SC_STRIDE;      // [QR][HD_]
    float* kv = qs + QR * HD_;                    // [SKV][HD_]

    const int b  = blockIdx.z;
    const int h  = blockIdx.y;
    const int qt = blockIdx.x;
    const int tid = threadIdx.x;

    const float scale = 0.125f;   // 1/sqrt(64)

    // load Q tile [QR][HD_]
    const float* Qbase = Q + ((size_t)(b * S_ + qt * QR)) * D_ + h * HD_;
    for (int i = tid; i < QR * HD_; i += 256) {
        int r = i >> 6, d = i & 63;
        qs[r * HD_ + d] = Qbase[(size_t)r * D_ + d];
    }

    const int qi = tid >> 3;          // 0..31 query row
    const int kb = (tid & 7) * 4;     // 4 keys per thread within chunk

    // ---- scores = Q K^T * scale ----
    const float* Kbase = K + ((size_t)b * S_) * D_ + h * HD_;
    for (int kt = 0; kt < S_; kt += SKV) {
        __syncthreads();
        for (int i = tid; i < SKV * HD_; i += 256) {
            int r = i >> 6, d = i & 63;
            kv[r * HD_ + d] = Kbase[(size_t)(kt + r) * D_ + d];
        }
        __syncthreads();
        float a0 = 0.f, a1 = 0.f, a2 = 0.f, a3 = 0.f;
        #pragma unroll 8
        for (int d = 0; d < HD_; d++) {
            float qv = qs[qi * HD_ + d];
            a0 += qv * kv[(kb + 0) * HD_ + d];
            a1 += qv * kv[(kb + 1) * HD_ + d];
            a2 += qv * kv[(kb + 2) * HD_ + d];
            a3 += qv * kv[(kb + 3) * HD_ + d];
        }
        float* srow = sc + (size_t)qi * SC_STRIDE + kt + kb;
        srow[0] = a0 * scale; srow[1] = a1 * scale;
        srow[2] = a2 * scale; srow[3] = a3 * scale;
    }
    __syncthreads();

    // ---- softmax per row: 8 lanes per row ----
    {
        const int lane = tid & 7;
        float* row = sc + (size_t)qi * SC_STRIDE;
        float m = -1e30f;
        for (int j = lane; j < S_; j += 8) m = fmaxf(m, row[j]);
        #pragma unroll
        for (int o = 4; o > 0; o >>= 1) m = fmaxf(m, __shfl_xor_sync(0xffffffffu, m, o));
        float sum = 0.f;
        for (int j = lane; j < S_; j += 8) {
            float e = __expf(row[j] - m);
            row[j] = e;
            sum += e;
        }
        #pragma unroll
        for (int o = 4; o > 0; o >>= 1) sum += __shfl_xor_sync(0xffffffffu, sum, o);
        float inv = 1.f / sum;
        for (int j = lane; j < S_; j += 8) row[j] *= inv;
    }
    __syncthreads();

    // ---- write normalized attn (coalesced) ----
    if (attn) {
        float* abase = attn + (((size_t)(b * H_ + h)) * S_ + qt * QR) * S_;
        for (int i = tid; i < QR * S_; i += 256) {
            int r = i >> 10, c = i & 1023;
            abase[i] = sc[(size_t)r * SC_STRIDE + c];
        }
    }

    // ---- ctx = attn @ V ----
    const int db = (tid & 7) * 8;     // 8 head-dims per thread
    float cacc[8];
    #pragma unroll
    for (int j = 0; j < 8; j++) cacc[j] = 0.f;

    const float* Vbase = V + ((size_t)b * S_) * D_ + h * HD_;
    for (int kt = 0; kt < S_; kt += SKV) {
        __syncthreads();
        for (int i = tid; i < SKV * HD_; i += 256) {
            int r = i >> 6, d = i & 63;
            kv[r * HD_ + d] = Vbase[(size_t)(kt + r) * D_ + d];
        }
        __syncthreads();
        #pragma unroll 8
        for (int kk = 0; kk < SKV; kk++) {
            float a = sc[(size_t)qi * SC_STRIDE + kt + kk];
            #pragma unroll
            for (int j = 0; j < 8; j++) cacc[j] += a * kv[kk * HD_ + db + j];
        }
    }

    float* cbase = ctx + ((size_t)(b * S_ + qt * QR)) * D_ + h * HD_;
    float* crow = cbase + (size_t)qi * D_ + db;
    #pragma unroll
    for (int j = 0; j < 8; j += 4)
        *(float4*)(crow + j) = make_float4(cacc[j], cacc[j+1], cacc[j+2], cacc[j+3]);
}

// ---------------------------------------------------------------------------
extern "C" void kernel_launch(void* const* d_in, const int* in_sizes, int n_in,
                              void* d_out, int out_size) {
    const float* x  = (const float*)d_in[0];
    const float* Wq = (const float*)d_in[1];
    const float* bq = (const float*)d_in[2];
    const float* Wk = (const float*)d_in[3];
    const float* bk = (const float*)d_in[4];
    const float* Wv = (const float*)d_in[5];
    const float* bv = (const float*)d_in[6];
    const float* Wo = (const float*)d_in[7];
    const float* bo = (const float*)d_in[8];

    float* out = (float*)d_out;

    const size_t OUT_ELEMS  = (size_t)B_ * S_ * D_;              // 8388608
    const size_t ATTN_ELEMS = (size_t)B_ * H_ * S_ * S_;         // 134217728
    float* attn_ptr = nullptr;
    if ((size_t)out_size >= OUT_ELEMS + ATTN_ELEMS)
        attn_ptr = out + OUT_ELEMS;                              // (out, attn) order

    float* Qb; cudaGetSymbolAddress((void**)&Qb, g_Q);
    float* Kb; cudaGetSymbolAddress((void**)&Kb, g_K);
    float* Vb; cudaGetSymbolAddress((void**)&Vb, g_V);
    float* Cb; cudaGetSymbolAddress((void**)&Cb, g_C);

    dim3 gGemm(D_ / BN, MROWS / BM);   // (8, 64)
    sgemm_atb_bias<<<gGemm, 256>>>(x, Wq, bq, Qb, MROWS, D_, D_);
    sgemm_atb_bias<<<gGemm, 256>>>(x, Wk, bk, Kb, MROWS, D_, D_);
    sgemm_atb_bias<<<gGemm, 256>>>(x, Wv, bv, Vb, MROWS, D_, D_);

    // fused attention
    static bool attr_set = false;
    size_t smem = ((size_t)QR * SC_STRIDE + QR * HD_ + SKV * HD_) * sizeof(float);
    cudaFuncSetAttribute(attn_kernel, cudaFuncAttributeMaxDynamicSharedMemorySize,
                         (int)smem);
    dim3 gAttn(S_ / QR, H_, B_);       // (32, 16, 8)
    attn_kernel<<<gAttn, 256, smem>>>(Qb, Kb, Vb, attn_ptr, Cb);

    // output projection
    sgemm_atb_bias<<<gGemm, 256>>>(Cb, Wo, bo, out, MROWS, D_, D_);
    (void)attr_set; (void)n_in; (void)in_sizes;
}

// round 2
// speedup vs baseline: 4.6019x; 4.6019x over previous
#include <cuda_runtime.h>
#include <cstdint>

// Problem constants
#define B_   8
#define S_   1024
#define D_   1024
#define H_   16
#define HD_  64
#define MROWS (B_ * S_)      // 8192

// ---------------- scratch (static device globals) ---------------------------
__device__ float g_Q[(size_t)MROWS * D_];
__device__ float g_K[(size_t)MROWS * D_];
__device__ float g_V[(size_t)MROWS * D_];
__device__ float g_C[(size_t)MROWS * D_];   // attention context

// ============================================================================
// Projection GEMM: C[m,n] = sum_k A[m,k]*W[n,k] + bias[n]
// M=8192, N=1024, K=1024. 128x128 tile, BK=16, 8x8 per thread (split 4+4).
// ============================================================================
#define SST 132   // smem row stride (m-dim 128 + 4 pad): kills transpose-store conflicts

__global__ __launch_bounds__(256, 2)
void proj_gemm(const float* __restrict__ A, const float* __restrict__ W,
               const float* __restrict__ bias, float* __restrict__ C) {
    __shared__ float As[16 * SST];
    __shared__ float Ws[16 * SST];

    const int tid = threadIdx.x;
    const int tx  = tid & 15;
    const int ty  = tid >> 4;
    const int m0  = blockIdx.y * 128;
    const int n0  = blockIdx.x * 128;

    const int lrow = tid >> 1;        // 0..127
    const int lc   = (tid & 1);       // 0/1

    const float* Ap = A + (size_t)(m0 + lrow) * D_;
    const float* Wp = W + (size_t)(n0 + lrow) * D_;

    float acc[8][8];
    #pragma unroll
    for (int i = 0; i < 8; i++)
        #pragma unroll
        for (int j = 0; j < 8; j++) acc[i][j] = 0.f;

    for (int k0 = 0; k0 < D_; k0 += 16) {
        // load: each thread 2 float4 per operand, transposed store
        #pragma unroll
        for (int j = 0; j < 2; j++) {
            int c = 4 * (lc + 2 * j);              // 0,8 / 4,12
            float4 av = *(const float4*)(Ap + k0 + c);
            float4 wv = *(const float4*)(Wp + k0 + c);
            As[(c + 0) * SST + lrow] = av.x;
            As[(c + 1) * SST + lrow] = av.y;
            As[(c + 2) * SST + lrow] = av.z;
            As[(c + 3) * SST + lrow] = av.w;
            Ws[(c + 0) * SST + lrow] = wv.x;
            Ws[(c + 1) * SST + lrow] = wv.y;
            Ws[(c + 2) * SST + lrow] = wv.z;
            Ws[(c + 3) * SST + lrow] = wv.w;
        }
        __syncthreads();

        #pragma unroll
        for (int kk = 0; kk < 16; kk++) {
            float a[8], w[8];
            float4 a0 = *(const float4*)&As[kk * SST + ty * 4];
            float4 a1 = *(const float4*)&As[kk * SST + 64 + ty * 4];
            float4 w0 = *(const float4*)&Ws[kk * SST + tx * 4];
            float4 w1 = *(const float4*)&Ws[kk * SST + 64 + tx * 4];
            a[0]=a0.x; a[1]=a0.y; a[2]=a0.z; a[3]=a0.w;
            a[4]=a1.x; a[5]=a1.y; a[6]=a1.z; a[7]=a1.w;
            w[0]=w0.x; w[1]=w0.y; w[2]=w0.z; w[3]=w0.w;
            w[4]=w1.x; w[5]=w1.y; w[6]=w1.z; w[7]=w1.w;
            #pragma unroll
            for (int i = 0; i < 8; i++)
                #pragma unroll
                for (int j = 0; j < 8; j++) acc[i][j] += a[i] * w[j];
        }
        __syncthreads();
    }

    float b0[4], b1[4];
    #pragma unroll
    for (int q = 0; q < 4; q++) {
        b0[q] = bias[n0 + tx * 4 + q];
        b1[q] = bias[n0 + 64 + tx * 4 + q];
    }

    #pragma unroll
    for (int i = 0; i < 8; i++) {
        int row = m0 + ((i < 4) ? (ty * 4 + i) : (64 + ty * 4 + i - 4));
        float* cr = C + (size_t)row * D_ + n0;
        *(float4*)(cr + tx * 4) =
            make_float4(acc[i][0] + b0[0], acc[i][1] + b0[1],
                        acc[i][2] + b0[2], acc[i][3] + b0[3]);
        *(float4*)(cr + 64 + tx * 4) =
            make_float4(acc[i][4] + b1[0], acc[i][5] + b1[1],
                        acc[i][6] + b1[2], acc[i][7] + b1[3]);
    }
}

// ============================================================================
// Score GEMM: scores[bh, q, k] = 0.125 * sum_d Q[bh,q,d]*K[bh,k,d]
// Batched 128x128x64 GEMM. Writes raw scaled scores into the attn buffer.
// ============================================================================
__global__ __launch_bounds__(256, 2)
void score_gemm(const float* __restrict__ Q, const float* __restrict__ Km,
                float* __restrict__ attn) {
    extern __shared__ float sm[];
    float* Qs = sm;                 // [64][SST]
    float* Ks = sm + 64 * SST;      // [64][SST]

    const int tid = threadIdx.x;
    const int tx  = tid & 15;
    const int ty  = tid >> 4;
    const int nt  = blockIdx.x;
    const int mt  = blockIdx.y;
    const int bh  = blockIdx.z;
    const int b   = bh >> 4;
    const int h   = bh & 15;

    const int lrow = tid >> 1;
    const int lc   = (tid & 1);

    const float* Qp = Q + ((size_t)(b * S_ + mt * 128 + lrow)) * D_ + h * HD_;
    const float* Kp = Km + ((size_t)(b * S_ + nt * 128 + lrow)) * D_ + h * HD_;

    // load Q,K tiles [128 rows][64 cols] transposed into smem [kk][row]
    #pragma unroll
    for (int j = 0; j < 8; j++) {
        int c = 4 * (lc + 2 * j);            // 0..60
        float4 qv = *(const float4*)(Qp + c);
        float4 kv = *(const float4*)(Kp + c);
        Qs[(c + 0) * SST + lrow] = qv.x;
        Qs[(c + 1) * SST + lrow] = qv.y;
        Qs[(c + 2) * SST + lrow] = qv.z;
        Qs[(c + 3) * SST + lrow] = qv.w;
        Ks[(c + 0) * SST + lrow] = kv.x;
        Ks[(c + 1) * SST + lrow] = kv.y;
        Ks[(c + 2) * SST + lrow] = kv.z;
        Ks[(c + 3) * SST + lrow] = kv.w;
    }
    __syncthreads();

    float acc[8][8];
    #pragma unroll
    for (int i = 0; i < 8; i++)
        #pragma unroll
        for (int j = 0; j < 8; j++) acc[i][j] = 0.f;

    #pragma unroll 8
    for (int kk = 0; kk < 64; kk++) {
        float a[8], w[8];
        float4 a0 = *(const float4*)&Qs[kk * SST + ty * 4];
        float4 a1 = *(const float4*)&Qs[kk * SST + 64 + ty * 4];
        float4 w0 = *(const float4*)&Ks[kk * SST + tx * 4];
        float4 w1 = *(const float4*)&Ks[kk * SST + 64 + tx * 4];
        a[0]=a0.x; a[1]=a0.y; a[2]=a0.z; a[3]=a0.w;
        a[4]=a1.x; a[5]=a1.y; a[6]=a1.z; a[7]=a1.w;
        w[0]=w0.x; w[1]=w0.y; w[2]=w0.z; w[3]=w0.w;
        w[4]=w1.x; w[5]=w1.y; w[6]=w1.z; w[7]=w1.w;
        #pragma unroll
        for (int i = 0; i < 8; i++)
            #pragma unroll
            for (int j = 0; j < 8; j++) acc[i][j] += a[i] * w[j];
    }

    #pragma unroll
    for (int i = 0; i < 8; i++) {
        int row = mt * 128 + ((i < 4) ? (ty * 4 + i) : (64 + ty * 4 + i - 4));
        float* cr = attn + ((size_t)bh * S_ + row) * S_ + nt * 128;
        *(float4*)(cr + tx * 4) =
            make_float4(acc[i][0]*0.125f, acc[i][1]*0.125f,
                        acc[i][2]*0.125f, acc[i][3]*0.125f);
        *(float4*)(cr + 64 + tx * 4) =
            make_float4(acc[i][4]*0.125f, acc[i][5]*0.125f,
                        acc[i][6]*0.125f, acc[i][7]*0.125f);
    }
}

// ============================================================================
// Softmax + AV: per (bh, 128-q strip).
// Phase 1: online row max + expsum over the 128x1024 raw-score strip.
// Phase 2: per 128-k tile: p = exp(s-m)/l, write attn in place, ctx += P@V.
// ============================================================================
#define PTS 129   // Pt smem stride (transposed P): conflict-free scatter stores
#define VSS 68    // Vs smem stride

__global__ __launch_bounds__(256, 2)
void softmax_av(float* __restrict__ attn, const float* __restrict__ V,
                float* __restrict__ ctx) {
    extern __shared__ float sm[];
    float* Pt = sm;                      // [128 k][PTS] (transposed P)
    float* Vs = Pt + 128 * PTS;          // [128 k][VSS]
    float* rm = Vs + 128 * VSS;          // [128] row max
    float* rl = rm + 128;                // [128] 1/row sum

    const int tid = threadIdx.x;
    const int qt  = blockIdx.x;
    const int bh  = blockIdx.y;
    const int b   = bh >> 4;
    const int h   = bh & 15;

    float* SC = attn + ((size_t)bh * S_ + qt * 128) * S_;

    // ---- phase 1: row stats (online softmax over 1024 cols) ----
    {
        const int sub = tid & 15;        // 16 threads per row, coalesced
        const int rr  = tid >> 4;
        for (int i = 0; i < 8; i++) {
            int r = i * 16 + rr;
            const float4* rp = (const float4*)(SC + (size_t)r * S_);
            float m = -1e30f, l = 0.f;
            #pragma unroll 4
            for (int j = 0; j < 16; j++) {
                float4 v = rp[sub + j * 16];
                float m4 = fmaxf(fmaxf(v.x, v.y), fmaxf(v.z, v.w));
                if (m4 > m) { l *= __expf(m - m4); m = m4; }
                l += __expf(v.x - m) + __expf(v.y - m)
                   + __expf(v.z - m) + __expf(v.w - m);
            }
            #pragma unroll
            for (int o = 8; o > 0; o >>= 1) {
                float mo = __shfl_xor_sync(0xffffffffu, m, o);
                float lo = __shfl_xor_sync(0xffffffffu, l, o);
                float mn = fmaxf(m, mo);
                l = l * __expf(m - mn) + lo * __expf(mo - mn);
                m = mn;
            }
            if (sub == 0) { rm[r] = m; rl[r] = 1.f / l; }
        }
    }
    __syncthreads();

    // ---- phase 2: normalize + write attn + ctx = P @ V ----
    const int mg = tid >> 3;     // 0..31 -> rows mg*4..mg*4+3
    const int dg = tid & 7;      // 0..7  -> dims dg*8..dg*8+7
    const float* Vp = V + ((size_t)b * S_) * D_ + h * HD_;

    float acc[4][8];
    #pragma unroll
    for (int i = 0; i < 4; i++)
        #pragma unroll
        for (int j = 0; j < 8; j++) acc[i][j] = 0.f;

    for (int kt = 0; kt < 8; kt++) {
        __syncthreads();
        // load score tile, exp-normalize, write attn in place, stash P^T
        #pragma unroll
        for (int ii = 0; ii < 4; ii++) {
            int r = ii * 32 + (tid >> 3);
            float m  = rm[r];
            float il = rl[r];
            float4* rp = (float4*)(SC + (size_t)r * S_ + kt * 128);
            #pragma unroll
            for (int j = 0; j < 4; j++) {
                int c4 = (tid & 7) + j * 8;
                float4 s = rp[c4];
                float4 p;
                p.x = __expf(s.x - m) * il;
                p.y = __expf(s.y - m) * il;
                p.z = __expf(s.z - m) * il;
                p.w = __expf(s.w - m) * il;
                rp[c4] = p;
                int c = c4 * 4;
                Pt[(c + 0) * PTS + r] = p.x;
                Pt[(c + 1) * PTS + r] = p.y;
                Pt[(c + 2) * PTS + r] = p.z;
                Pt[(c + 3) * PTS + r] = p.w;
            }
        }
        // load V tile [128][64]
        {
            int r = tid >> 1;
            const float4* vp = (const float4*)(Vp + (size_t)(kt * 128 + r) * D_);
            #pragma unroll
            for (int j = 0; j < 8; j++) {
                int c4 = (tid & 1) * 8 + j;
                float4 v = vp[c4];
                *(float4*)&Vs[r * VSS + c4 * 4] = v;
            }
        }
        __syncthreads();

        #pragma unroll 4
        for (int kk = 0; kk < 128; kk++) {
            float a0 = Pt[kk * PTS + mg * 4 + 0];
            float a1 = Pt[kk * PTS + mg * 4 + 1];
            float a2 = Pt[kk * PTS + mg * 4 + 2];
            float a3 = Pt[kk * PTS + mg * 4 + 3];
            float4 v0 = *(const float4*)&Vs[kk * VSS + dg * 8];
            float4 v1 = *(const float4*)&Vs[kk * VSS + dg * 8 + 4];
            float w[8] = {v0.x, v0.y, v0.z, v0.w, v1.x, v1.y, v1.z, v1.w};
            #pragma unroll
            for (int j = 0; j < 8; j++) {
                acc[0][j] += a0 * w[j];
                acc[1][j] += a1 * w[j];
                acc[2][j] += a2 * w[j];
                acc[3][j] += a3 * w[j];
            }
        }
    }

    float* cb = ctx + ((size_t)(b * S_ + qt * 128 + mg * 4)) * D_ + h * HD_ + dg * 8;
    #pragma unroll
    for (int i = 0; i < 4; i++) {
        *(float4*)(cb + (size_t)i * D_)     = make_float4(acc[i][0], acc[i][1], acc[i][2], acc[i][3]);
        *(float4*)(cb + (size_t)i * D_ + 4) = make_float4(acc[i][4], acc[i][5], acc[i][6], acc[i][7]);
    }
}

// ---------------------------------------------------------------------------
extern "C" void kernel_launch(void* const* d_in, const int* in_sizes, int n_in,
                              void* d_out, int out_size) {
    const float* x  = (const float*)d_in[0];
    const float* Wq = (const float*)d_in[1];
    const float* bq = (const float*)d_in[2];
    const float* Wk = (const float*)d_in[3];
    const float* bk = (const float*)d_in[4];
    const float* Wv = (const float*)d_in[5];
    const float* bv = (const float*)d_in[6];
    const float* Wo = (const float*)d_in[7];
    const float* bo = (const float*)d_in[8];

    float* out = (float*)d_out;
    const size_t OUT_ELEMS = (size_t)B_ * S_ * D_;
    float* attn_ptr = out + OUT_ELEMS;   // (out, attn) concatenated

    float* Qb; cudaGetSymbolAddress((void**)&Qb, g_Q);
    float* Kb; cudaGetSymbolAddress((void**)&Kb, g_K);
    float* Vb; cudaGetSymbolAddress((void**)&Vb, g_V);
    float* Cb; cudaGetSymbolAddress((void**)&Cb, g_C);

    // projections
    dim3 gProj(D_ / 128, MROWS / 128);   // (8, 64)
    proj_gemm<<<gProj, 256>>>(x, Wq, bq, Qb);
    proj_gemm<<<gProj, 256>>>(x, Wk, bk, Kb);
    proj_gemm<<<gProj, 256>>>(x, Wv, bv, Vb);

    // scores -> attn buffer (raw, scaled)
    size_t smem_sc = (size_t)2 * 64 * SST * sizeof(float);   // 67.6KB
    cudaFuncSetAttribute(score_gemm, cudaFuncAttributeMaxDynamicSharedMemorySize,
                         (int)smem_sc);
    dim3 gScore(S_ / 128, S_ / 128, B_ * H_);   // (8, 8, 128)
    score_gemm<<<gScore, 256, smem_sc>>>(Qb, Kb, attn_ptr);

    // softmax (in-place on attn) + ctx = P @ V
    size_t smem_av = ((size_t)128 * PTS + 128 * VSS + 256) * sizeof(float);  // ~102KB
    cudaFuncSetAttribute(softmax_av, cudaFuncAttributeMaxDynamicSharedMemorySize,
                         (int)smem_av);
    dim3 gAV(S_ / 128, B_ * H_);                // (8, 128)
    softmax_av<<<gAV, 256, smem_av>>>(attn_ptr, Vb, Cb);

    // output projection
    proj_gemm<<<gProj, 256>>>(Cb, Wo, bo, out);

    (void)n_in; (void)in_sizes; (void)out_size;
}

// round 5
// speedup vs baseline: 6.6139x; 1.4372x over previous
#include <cuda_runtime.h>
#include <cstdint>

// Problem constants
#define B_   8
#define S_   1024
#define D_   1024
#define H_   16
#define HD_  64
#define MROWS (B_ * S_)      // 8192

// ---------------- scratch (static device globals) ---------------------------
__device__ float g_Q[(size_t)MROWS * D_];
__device__ float g_K[(size_t)MROWS * D_];
__device__ float g_V[(size_t)MROWS * D_];
__device__ float g_C[(size_t)MROWS * D_];   // attention context

// ============================================================================
// Helpers
// ============================================================================
__device__ __forceinline__ float tf32_rna(float x) {
    uint32_t u;
    asm("cvt.rna.tf32.f32 %0, %1;" : "=r"(u) : "f"(x));
    return __uint_as_float(u);
}

// D += A(16x8) * B(8x8), tf32 operands in b32 regs, fp32 accum
__device__ __forceinline__ void mma_tf32(float* d, const float* a2, const float* b2) {
    asm volatile(
        "mma.sync.aligned.m16n8k8.row.col.f32.tf32.tf32.f32 "
        "{%0,%1,%2,%3}, {%4,%5,%6,%7}, {%8,%9}, {%0,%1,%2,%3};"
        : "+f"(d[0]), "+f"(d[1]), "+f"(d[2]), "+f"(d[3])
        : "r"(__float_as_uint(a2[0])), "r"(__float_as_uint(a2[1])),
          "r"(__float_as_uint(a2[2])), "r"(__float_as_uint(a2[3])),
          "r"(__float_as_uint(b2[0])), "r"(__float_as_uint(b2[1])));
}

// fast exp on the FFMA pipe (no MUFU). |rel err| < 3e-6 over clamped range.
__device__ __forceinline__ float fast_exp(float x) {
    x = fminf(fmaxf(x, -80.f), 80.f);
    float y = x * 1.44269504088896341f;
    float nf = rintf(y);
    float f = y - nf;
    float p = 1.33335581e-3f;
    p = fmaf(p, f, 9.61812911e-3f);
    p = fmaf(p, f, 5.55041087e-2f);
    p = fmaf(p, f, 2.40226507e-1f);
    p = fmaf(p, f, 6.93147180e-1f);
    p = fmaf(p, f, 1.0f);
    int i = (int)nf;
    return p * __int_as_float((127 + i) << 23);
}

// ============================================================================
// Projection GEMM via tf32 mma.sync: C[m,n] = sum_k A[m,k]*W[n,k] + bias[n]
// CTA 128x128, BK=16, 3-stage smem pipeline, warp tile 32x64 (4m x 2n warps).
// ============================================================================
#define PST  136                    // smem k-row stride (floats)
#define SZA  (16 * PST)             // one stage, one operand (floats)
#define PROJ_SMEM (6 * SZA * 4)     // 3 stages x (A + W) = 52224 bytes

__global__ __launch_bounds__(256)
void proj_mma(const float* __restrict__ A, const float* __restrict__ W,
              const float* __restrict__ bias, float* __restrict__ C) {
    extern __shared__ float sm[];
    float* SA = sm;                 // 3 stages A
    float* SW = sm + 3 * SZA;       // 3 stages W

    const int tid = threadIdx.x;
    const int wid = tid >> 5;
    const int lane = tid & 31;
    const int g = lane >> 2;        // 0..7
    const int t = lane & 3;         // 0..3
    const int wm = (wid & 3) * 32;  // warp m offset
    const int wn = (wid >> 2) * 64; // warp n offset
    const int m0 = blockIdx.y * 128;
    const int n0 = blockIdx.x * 128;

    const int lrow = tid >> 1;            // 0..127
    const int lk0  = (tid & 1) * 8;       // 0 or 8

    const float* Ap = A + (size_t)(m0 + lrow) * D_ + lk0;
    const float* Wp = W + (size_t)(n0 + lrow) * D_ + lk0;

    float acc[2][8][4];
    #pragma unroll
    for (int i = 0; i < 2; i++)
        #pragma unroll
        for (int j = 0; j < 8; j++)
            #pragma unroll
            for (int q = 0; q < 4; q++) acc[i][j][q] = 0.f;

    float4 ra0, ra1, rw0, rw1;
    // LDG chunk 0
    ra0 = *(const float4*)(Ap);     ra1 = *(const float4*)(Ap + 4);
    rw0 = *(const float4*)(Wp);     rw1 = *(const float4*)(Wp + 4);
    // STS chunk 0 -> stage 0
    {
        float* as = SA; float* ws = SW;
        as[(lk0+0)*PST + lrow] = tf32_rna(ra0.x); as[(lk0+1)*PST + lrow] = tf32_rna(ra0.y);
        as[(lk0+2)*PST + lrow] = tf32_rna(ra0.z); as[(lk0+3)*PST + lrow] = tf32_rna(ra0.w);
        as[(lk0+4)*PST + lrow] = tf32_rna(ra1.x); as[(lk0+5)*PST + lrow] = tf32_rna(ra1.y);
        as[(lk0+6)*PST + lrow] = tf32_rna(ra1.z); as[(lk0+7)*PST + lrow] = tf32_rna(ra1.w);
        ws[(lk0+0)*PST + lrow] = tf32_rna(rw0.x); ws[(lk0+1)*PST + lrow] = tf32_rna(rw0.y);
        ws[(lk0+2)*PST + lrow] = tf32_rna(rw0.z); ws[(lk0+3)*PST + lrow] = tf32_rna(rw0.w);
        ws[(lk0+4)*PST + lrow] = tf32_rna(rw1.x); ws[(lk0+5)*PST + lrow] = tf32_rna(rw1.y);
        ws[(lk0+6)*PST + lrow] = tf32_rna(rw1.z); ws[(lk0+7)*PST + lrow] = tf32_rna(rw1.w);
    }
    // LDG chunk 1
    ra0 = *(const float4*)(Ap + 16);  ra1 = *(const float4*)(Ap + 20);
    rw0 = *(const float4*)(Wp + 16);  rw1 = *(const float4*)(Wp + 20);
    __syncthreads();

    for (int c = 0; c < 64; c++) {
        // STS chunk c+1 -> stage (c+1)%3
        if (c + 1 < 64) {
            int s = (c + 1) % 3;
            float* as = SA + s * SZA; float* ws = SW + s * SZA;
            as[(lk0+0)*PST + lrow] = tf32_rna(ra0.x); as[(lk0+1)*PST + lrow] = tf32_rna(ra0.y);
            as[(lk0+2)*PST + lrow] = tf32_rna(ra0.z); as[(lk0+3)*PST + lrow] = tf32_rna(ra0.w);
            as[(lk0+4)*PST + lrow] = tf32_rna(ra1.x); as[(lk0+5)*PST + lrow] = tf32_rna(ra1.y);
            as[(lk0+6)*PST + lrow] = tf32_rna(ra1.z); as[(lk0+7)*PST + lrow] = tf32_rna(ra1.w);
            ws[(lk0+0)*PST + lrow] = tf32_rna(rw0.x); ws[(lk0+1)*PST + lrow] = tf32_rna(rw0.y);
            ws[(lk0+2)*PST + lrow] = tf32_rna(rw0.z); ws[(lk0+3)*PST + lrow] = tf32_rna(rw0.w);
            ws[(lk0+4)*PST + lrow] = tf32_rna(rw1.x); ws[(lk0+5)*PST + lrow] = tf32_rna(rw1.y);
            ws[(lk0+6)*PST + lrow] = tf32_rna(rw1.z); ws[(lk0+7)*PST + lrow] = tf32_rna(rw1.w);
        }
        // LDG chunk c+2
        if (c + 2 < 64) {
            ra0 = *(const float4*)(Ap + (c + 2) * 16);
            ra1 = *(const float4*)(Ap + (c + 2) * 16 + 4);
            rw0 = *(const float4*)(Wp + (c + 2) * 16);
            rw1 = *(const float4*)(Wp + (c + 2) * 16 + 4);
        }
        // MMA on stage c%3
        {
            const float* as = SA + (c % 3) * SZA;
            const float* ws = SW + (c % 3) * SZA;
            #pragma unroll
            for (int ks = 0; ks < 2; ks++) {
                int kk = ks * 8;
                float af[2][4];
                #pragma unroll
                for (int ms = 0; ms < 2; ms++) {
                    int mb = wm + ms * 16;
                    af[ms][0] = as[(kk + t)     * PST + mb + g];
                    af[ms][1] = as[(kk + t)     * PST + mb + g + 8];
                    af[ms][2] = as[(kk + t + 4) * PST + mb + g];
                    af[ms][3] = as[(kk + t + 4) * PST + mb + g + 8];
                }
                #pragma unroll
                for (int j = 0; j < 8; j++) {
                    float bf[2];
                    bf[0] = ws[(kk + t)     * PST + wn + j * 8 + g];
                    bf[1] = ws[(kk + t + 4) * PST + wn + j * 8 + g];
                    mma_tf32(acc[0][j], af[0], bf);
                    mma_tf32(acc[1][j], af[1], bf);
                }
            }
        }
        __syncthreads();
    }

    // epilogue: bias + store
    #pragma unroll
    for (int j = 0; j < 8; j++) {
        int col = n0 + wn + j * 8 + 2 * t;
        float2 bv = *(const float2*)(bias + col);
        #pragma unroll
        for (int ms = 0; ms < 2; ms++) {
            int r0 = m0 + wm + ms * 16 + g;
            float2 v0 = make_float2(acc[ms][j][0] + bv.x, acc[ms][j][1] + bv.y);
            float2 v1 = make_float2(acc[ms][j][2] + bv.x, acc[ms][j][3] + bv.y);
            *(float2*)(C + (size_t)r0 * D_ + col)       = v0;
            *(float2*)(C + (size_t)(r0 + 8) * D_ + col) = v1;
        }
    }
}

// ============================================================================
// Score GEMM via tf32 mma.sync: attn_raw[bh,q,k] = 0.125 * sum_d Q*K
// CTA 128x128, K=64 single-shot. Same warp tiling as proj.
// ============================================================================
#define SCORE_SMEM (2 * 64 * PST * 4)   // 69632 bytes

__global__ __launch_bounds__(256)
void score_mma(const float* __restrict__ Q, const float* __restrict__ Km,
               float* __restrict__ attn) {
    extern __shared__ float sm[];
    float* Qs = sm;                  // [64][PST]
    float* Ks = sm + 64 * PST;

    const int tid = threadIdx.x;
    const int wid = tid >> 5;
    const int lane = tid & 31;
    const int g = lane >> 2;
    const int t = lane & 3;
    const int wm = (wid & 3) * 32;
    const int wn = (wid >> 2) * 64;
    const int nt = blockIdx.x;
    const int mt = blockIdx.y;
    const int bh = blockIdx.z;
    const int b  = bh >> 4;
    const int h  = bh & 15;

    const int lrow = tid >> 1;
    const int lk0  = (tid & 1) * 32;

    const float* Qp = Q + ((size_t)(b * S_ + mt * 128 + lrow)) * D_ + h * HD_ + lk0;
    const float* Kp = Km + ((size_t)(b * S_ + nt * 128 + lrow)) * D_ + h * HD_ + lk0;

    #pragma unroll
    for (int j = 0; j < 8; j++) {
        float4 qv = *(const float4*)(Qp + j * 4);
        float4 kv = *(const float4*)(Kp + j * 4);
        int k = lk0 + j * 4;
        Qs[(k+0)*PST + lrow] = tf32_rna(qv.x); Qs[(k+1)*PST + lrow] = tf32_rna(qv.y);
        Qs[(k+2)*PST + lrow] = tf32_rna(qv.z); Qs[(k+3)*PST + lrow] = tf32_rna(qv.w);
        Ks[(k+0)*PST + lrow] = tf32_rna(kv.x); Ks[(k+1)*PST + lrow] = tf32_rna(kv.y);
        Ks[(k+2)*PST + lrow] = tf32_rna(kv.z); Ks[(k+3)*PST + lrow] = tf32_rna(kv.w);
    }
    __syncthreads();

    float acc[2][8][4];
    #pragma unroll
    for (int i = 0; i < 2; i++)
        #pragma unroll
        for (int j = 0; j < 8; j++)
            #pragma unroll
            for (int q = 0; q < 4; q++) acc[i][j][q] = 0.f;

    #pragma unroll
    for (int ks = 0; ks < 8; ks++) {
        int kk = ks * 8;
        float af[2][4];
        #pragma unroll
        for (int ms = 0; ms < 2; ms++) {
            int mb = wm + ms * 16;
            af[ms][0] = Qs[(kk + t)     * PST + mb + g];
            af[ms][1] = Qs[(kk + t)     * PST + mb + g + 8];
            af[ms][2] = Qs[(kk + t + 4) * PST + mb + g];
            af[ms][3] = Qs[(kk + t + 4) * PST + mb + g + 8];
        }
        #pragma unroll
        for (int j = 0; j < 8; j++) {
            float bf[2];
            bf[0] = Ks[(kk + t)     * PST + wn + j * 8 + g];
            bf[1] = Ks[(kk + t + 4) * PST + wn + j * 8 + g];
            mma_tf32(acc[0][j], af[0], bf);
            mma_tf32(acc[1][j], af[1], bf);
        }
    }

    // epilogue: *0.125, store
    #pragma unroll
    for (int j = 0; j < 8; j++) {
        int col = nt * 128 + wn + j * 8 + 2 * t;
        #pragma unroll
        for (int ms = 0; ms < 2; ms++) {
            int r0 = mt * 128 + wm + ms * 16 + g;
            float* base = attn + ((size_t)bh * S_ + r0) * S_ + col;
            *(float2*)(base) =
                make_float2(acc[ms][j][0] * 0.125f, acc[ms][j][1] * 0.125f);
            *(float2*)(base + (size_t)8 * S_) =
                make_float2(acc[ms][j][2] * 0.125f, acc[ms][j][3] * 0.125f);
        }
    }
}

// ============================================================================
// Softmax + AV (structure as R2; __expf -> fast_exp on FFMA pipe)
// ============================================================================
#define PTS 129
#define VSS 68

__global__ __launch_bounds__(256, 2)
void softmax_av(float* __restrict__ attn, const float* __restrict__ V,
                float* __restrict__ ctx) {
    extern __shared__ float smf[];
    float* Pt = smf;
    float* Vs = Pt + 128 * PTS;
    float* rm = Vs + 128 * VSS;
    float* rl = rm + 128;

    const int tid = threadIdx.x;
    const int qt  = blockIdx.x;
    const int bh  = blockIdx.y;
    const int b   = bh >> 4;
    const int h   = bh & 15;

    float* SC = attn + ((size_t)bh * S_ + qt * 128) * S_;

    {
        const int sub = tid & 15;
        const int rr  = tid >> 4;
        for (int i = 0; i < 8; i++) {
            int r = i * 16 + rr;
            const float4* rp = (const float4*)(SC + (size_t)r * S_);
            float m = -1e30f, l = 0.f;
            #pragma unroll 4
            for (int j = 0; j < 16; j++) {
                float4 v = rp[sub + j * 16];
                float m4 = fmaxf(fmaxf(v.x, v.y), fmaxf(v.z, v.w));
                if (m4 > m) { l *= fast_exp(m - m4); m = m4; }
                l += fast_exp(v.x - m) + fast_exp(v.y - m)
                   + fast_exp(v.z - m) + fast_exp(v.w - m);
            }
            #pragma unroll
            for (int o = 8; o > 0; o >>= 1) {
                float mo = __shfl_xor_sync(0xffffffffu, m, o);
                float lo = __shfl_xor_sync(0xffffffffu, l, o);
                float mn = fmaxf(m, mo);
                l = l * fast_exp(m - mn) + lo * fast_exp(mo - mn);
                m = mn;
            }
            if (sub == 0) { rm[r] = m; rl[r] = 1.f / l; }
        }
    }
    __syncthreads();

    const int mg = tid >> 3;
    const int dg = tid & 7;
    const float* Vp = V + ((size_t)b * S_) * D_ + h * HD_;

    float acc[4][8];
    #pragma unroll
    for (int i = 0; i < 4; i++)
        #pragma unroll
        for (int j = 0; j < 8; j++) acc[i][j] = 0.f;

    for (int kt = 0; kt < 8; kt++) {
        __syncthreads();
        #pragma unroll
        for (int ii = 0; ii < 4; ii++) {
            int r = ii * 32 + (tid >> 3);
            float m  = rm[r];
            float il = rl[r];
            float4* rp = (float4*)(SC + (size_t)r * S_ + kt * 128);
            #pragma unroll
            for (int j = 0; j < 4; j++) {
                int c4 = (tid & 7) + j * 8;
                float4 s = rp[c4];
                float4 p;
                p.x = fast_exp(s.x - m) * il;
                p.y = fast_exp(s.y - m) * il;
                p.z = fast_exp(s.z - m) * il;
                p.w = fast_exp(s.w - m) * il;
                rp[c4] = p;
                int c = c4 * 4;
                Pt[(c + 0) * PTS + r] = p.x;
                Pt[(c + 1) * PTS + r] = p.y;
                Pt[(c + 2) * PTS + r] = p.z;
                Pt[(c + 3) * PTS + r] = p.w;
            }
        }
        {
            int r = tid >> 1;
            const float4* vp = (const float4*)(Vp + (size_t)(kt * 128 + r) * D_);
            #pragma unroll
            for (int j = 0; j < 8; j++) {
                int c4 = (tid & 1) * 8 + j;
                float4 v = vp[c4];
                *(float4*)&Vs[r * VSS + c4 * 4] = v;
            }
        }
        __syncthreads();

        #pragma unroll 4
        for (int kk = 0; kk < 128; kk++) {
            float a0 = Pt[kk * PTS + mg * 4 + 0];
            float a1 = Pt[kk * PTS + mg * 4 + 1];
            float a2 = Pt[kk * PTS + mg * 4 + 2];
            float a3 = Pt[kk * PTS + mg * 4 + 3];
            float4 v0 = *(const float4*)&Vs[kk * VSS + dg * 8];
            float4 v1 = *(const float4*)&Vs[kk * VSS + dg * 8 + 4];
            float w[8] = {v0.x, v0.y, v0.z, v0.w, v1.x, v1.y, v1.z, v1.w};
            #pragma unroll
            for (int j = 0; j < 8; j++) {
                acc[0][j] += a0 * w[j];
                acc[1][j] += a1 * w[j];
                acc[2][j] += a2 * w[j];
                acc[3][j] += a3 * w[j];
            }
        }
    }

    float* cb = ctx + ((size_t)(b * S_ + qt * 128 + mg * 4)) * D_ + h * HD_ + dg * 8;
    #pragma unroll
    for (int i = 0; i < 4; i++) {
        *(float4*)(cb + (size_t)i * D_)     = make_float4(acc[i][0], acc[i][1], acc[i][2], acc[i][3]);
        *(float4*)(cb + (size_t)i * D_ + 4) = make_float4(acc[i][4], acc[i][5], acc[i][6], acc[i][7]);
    }
}

// ---------------------------------------------------------------------------
extern "C" void kernel_launch(void* const* d_in, const int* in_sizes, int n_in,
                              void* d_out, int out_size) {
    const float* x  = (const float*)d_in[0];
    const float* Wq = (const float*)d_in[1];
    const float* bq = (const float*)d_in[2];
    const float* Wk = (const float*)d_in[3];
    const float* bk = (const float*)d_in[4];
    const float* Wv = (const float*)d_in[5];
    const float* bv = (const float*)d_in[6];
    const float* Wo = (const float*)d_in[7];
    const float* bo = (const float*)d_in[8];

    float* out = (float*)d_out;
    const size_t OUT_ELEMS = (size_t)B_ * S_ * D_;
    float* attn_ptr = out + OUT_ELEMS;   // (out, attn) concatenated

    float* Qb; cudaGetSymbolAddress((void**)&Qb, g_Q);
    float* Kb; cudaGetSymbolAddress((void**)&Kb, g_K);
    float* Vb; cudaGetSymbolAddress((void**)&Vb, g_V);
    float* Cb; cudaGetSymbolAddress((void**)&Cb, g_C);

    size_t smem_av = ((size_t)128 * PTS + 128 * VSS + 256) * sizeof(float);
    cudaFuncSetAttribute(proj_mma, cudaFuncAttributeMaxDynamicSharedMemorySize, PROJ_SMEM);
    cudaFuncSetAttribute(score_mma, cudaFuncAttributeMaxDynamicSharedMemorySize, SCORE_SMEM);
    cudaFuncSetAttribute(softmax_av, cudaFuncAttributeMaxDynamicSharedMemorySize, (int)smem_av);

    // projections (tf32 mma.sync)
    dim3 gProj(D_ / 128, MROWS / 128);          // (8, 64)
    proj_mma<<<gProj, 256, PROJ_SMEM>>>(x, Wq, bq, Qb);
    proj_mma<<<gProj, 256, PROJ_SMEM>>>(x, Wk, bk, Kb);
    proj_mma<<<gProj, 256, PROJ_SMEM>>>(x, Wv, bv, Vb);

    // scores -> attn buffer (raw, scaled), tf32 mma.sync
    dim3 gScore(S_ / 128, S_ / 128, B_ * H_);   // (8, 8, 128)
    score_mma<<<gScore, 256, SCORE_SMEM>>>(Qb, Kb, attn_ptr);

    // softmax (in-place on attn) + ctx = P @ V
    dim3 gAV(S_ / 128, B_ * H_);                // (8, 128)
    softmax_av<<<gAV, 256, smem_av>>>(attn_ptr, Vb, Cb);

    // output projection
    proj_mma<<<gProj, 256, PROJ_SMEM>>>(Cb, Wo, bo, out);

    (void)n_in; (void)in_sizes; (void)out_size;
}

// round 8
// speedup vs baseline: 11.9846x; 1.8120x over previous
#include <cuda_runtime.h>
#include <cuda_fp16.h>
#include <cstdint>

// Problem constants
#define B_   8
#define S_   1024
#define D_   1024
#define H_   16
#define HD_  64
#define MROWS (B_ * S_)      // 8192

// ---------------- scratch (static device globals) ---------------------------
__device__ float g_Q[(size_t)MROWS * D_];
__device__ float g_K[(size_t)MROWS * D_];
__device__ float g_V[(size_t)MROWS * D_];
__device__ float g_C[(size_t)MROWS * D_];   // attention context

// ============================================================================
// Helpers
// ============================================================================
__device__ __forceinline__ uint32_t smem_u32(const void* p) {
    uint32_t a;
    asm("{ .reg .u64 t; cvta.to.shared.u64 t, %1; cvt.u32.u64 %0, t; }"
        : "=r"(a) : "l"(p));
    return a;
}
__device__ __forceinline__ uint32_t f2h2(float lo, float hi) {
    uint32_t r;
    asm("cvt.rn.f16x2.f32 %0, %1, %2;" : "=r"(r) : "f"(hi), "f"(lo));
    return r;
}
__device__ __forceinline__ void ldsm_x4(uint32_t& r0, uint32_t& r1,
                                        uint32_t& r2, uint32_t& r3, uint32_t a) {
    asm volatile("ldmatrix.sync.aligned.m8n8.x4.shared.b16 {%0,%1,%2,%3}, [%4];"
                 : "=r"(r0), "=r"(r1), "=r"(r2), "=r"(r3) : "r"(a));
}
__device__ __forceinline__ void ldsm_x4_t(uint32_t& r0, uint32_t& r1,
                                          uint32_t& r2, uint32_t& r3, uint32_t a) {
    asm volatile("ldmatrix.sync.aligned.m8n8.x4.trans.shared.b16 {%0,%1,%2,%3}, [%4];"
                 : "=r"(r0), "=r"(r1), "=r"(r2), "=r"(r3) : "r"(a));
}
// C(16x8,f32) += A(16x16,f16) * B(16x8,f16)
__device__ __forceinline__ void mma_f16(float* c, const uint32_t* a, const uint32_t* b) {
    asm volatile(
        "mma.sync.aligned.m16n8k16.row.col.f32.f16.f16.f32 "
        "{%0,%1,%2,%3}, {%4,%5,%6,%7}, {%8,%9}, {%0,%1,%2,%3};"
        : "+f"(c[0]), "+f"(c[1]), "+f"(c[2]), "+f"(c[3])
        : "r"(a[0]), "r"(a[1]), "r"(a[2]), "r"(a[3]), "r"(b[0]), "r"(b[1]));
}
// fast exp on the FFMA pipe (no MUFU)
__device__ __forceinline__ float fast_exp(float x) {
    x = fminf(fmaxf(x, -80.f), 80.f);
    float y = x * 1.44269504088896341f;
    float nf = rintf(y);
    float f = y - nf;
    float p = 1.33335581e-3f;
    p = fmaf(p, f, 9.61812911e-3f);
    p = fmaf(p, f, 5.55041087e-2f);
    p = fmaf(p, f, 2.40226507e-1f);
    p = fmaf(p, f, 6.93147180e-1f);
    p = fmaf(p, f, 1.0f);
    return p * __int_as_float((127 + (int)nf) << 23);
}

// ============================================================================
// Projection GEMM, fp16 mma.sync m16n8k16 + ldmatrix.
// C[m,n] = sum_k A[m,k]*W[n,k] + bias[n]. CTA 128x128, BK=32, double buffer.
// smem rows: 40 halfs (80B) -> conflict-free LDSM (banks 20m % 32 distinct).
// ============================================================================
#define PRS 40                         // halfs per smem row
#define PR_STAGE (128 * PRS)           // halfs per operand stage

__global__ __launch_bounds__(256)
void proj_f16(const float* __restrict__ A, const float* __restrict__ W,
              const float* __restrict__ bias, float* __restrict__ C) {
    __shared__ __half SA[2 * PR_STAGE];
    __shared__ __half SW[2 * PR_STAGE];
    const uint32_t sa = smem_u32(SA);
    const uint32_t sw = smem_u32(SW);

    const int tid = threadIdx.x;
    const int wid = tid >> 5;
    const int lane = tid & 31;
    const int wm = (wid & 3) * 32;
    const int wn = (wid >> 2) * 64;
    const int m0 = blockIdx.y * 128;
    const int n0 = blockIdx.x * 128;

    const int lrow = tid >> 1;          // 0..127
    const int lch  = (tid & 1) * 16;    // col offset within 32-chunk
    const float* Ap = A + (size_t)(m0 + lrow) * D_ + lch;
    const float* Wp = W + (size_t)(n0 + lrow) * D_ + lch;
    const uint32_t stsoff = (uint32_t)(lrow * PRS * 2 + (lch / 8) * 16);

    float acc[2][8][4];
    #pragma unroll
    for (int i = 0; i < 2; i++)
        #pragma unroll
        for (int j = 0; j < 8; j++)
            #pragma unroll
            for (int q = 0; q < 4; q++) acc[i][j][q] = 0.f;

    float4 ra[2], rw[2];
    // chunk 0 LDG + STS
    ra[0] = *(const float4*)(Ap);      ra[1] = *(const float4*)(Ap + 4);
    rw[0] = *(const float4*)(Wp);      rw[1] = *(const float4*)(Wp + 4);
    float4 ra2 = *(const float4*)(Ap + 8),  ra3 = *(const float4*)(Ap + 12);
    float4 rw2 = *(const float4*)(Wp + 8),  rw3 = *(const float4*)(Wp + 12);
    {
        uint4 va = {f2h2(ra[0].x, ra[0].y), f2h2(ra[0].z, ra[0].w),
                    f2h2(ra[1].x, ra[1].y), f2h2(ra[1].z, ra[1].w)};
        uint4 vb = {f2h2(ra2.x, ra2.y), f2h2(ra2.z, ra2.w),
                    f2h2(ra3.x, ra3.y), f2h2(ra3.z, ra3.w)};
        *(uint4*)((char*)SA + stsoff)      = va;
        *(uint4*)((char*)SA + stsoff + 16) = vb;
        uint4 wa = {f2h2(rw[0].x, rw[0].y), f2h2(rw[0].z, rw[0].w),
                    f2h2(rw[1].x, rw[1].y), f2h2(rw[1].z, rw[1].w)};
        uint4 wb = {f2h2(rw2.x, rw2.y), f2h2(rw2.z, rw2.w),
                    f2h2(rw3.x, rw3.y), f2h2(rw3.z, rw3.w)};
        *(uint4*)((char*)SW + stsoff)      = wa;
        *(uint4*)((char*)SW + stsoff + 16) = wb;
    }
    // LDG chunk 1
    ra[0] = *(const float4*)(Ap + 32); ra[1] = *(const float4*)(Ap + 36);
    ra2   = *(const float4*)(Ap + 40); ra3   = *(const float4*)(Ap + 44);
    rw[0] = *(const float4*)(Wp + 32); rw[1] = *(const float4*)(Wp + 36);
    rw2   = *(const float4*)(Wp + 40); rw3   = *(const float4*)(Wp + 44);
    __syncthreads();

    for (int c = 0; c < 32; c++) {
        // STS chunk c+1 into the other stage
        if (c + 1 < 32) {
            uint32_t so = (uint32_t)(((c + 1) & 1) * PR_STAGE * 2);
            uint4 va = {f2h2(ra[0].x, ra[0].y), f2h2(ra[0].z, ra[0].w),
                        f2h2(ra[1].x, ra[1].y), f2h2(ra[1].z, ra[1].w)};
            uint4 vb = {f2h2(ra2.x, ra2.y), f2h2(ra2.z, ra2.w),
                        f2h2(ra3.x, ra3.y), f2h2(ra3.z, ra3.w)};
            *(uint4*)((char*)SA + so + stsoff)      = va;
            *(uint4*)((char*)SA + so + stsoff + 16) = vb;
            uint4 wa = {f2h2(rw[0].x, rw[0].y), f2h2(rw[0].z, rw[0].w),
                        f2h2(rw[1].x, rw[1].y), f2h2(rw[1].z, rw[1].w)};
            uint4 wb = {f2h2(rw2.x, rw2.y), f2h2(rw2.z, rw2.w),
                        f2h2(rw3.x, rw3.y), f2h2(rw3.z, rw3.w)};
            *(uint4*)((char*)SW + so + stsoff)      = wa;
            *(uint4*)((char*)SW + so + stsoff + 16) = wb;
        }
        if (c + 2 < 32) {
            const float* ap = Ap + (c + 2) * 32;
            const float* wp = Wp + (c + 2) * 32;
            ra[0] = *(const float4*)(ap);     ra[1] = *(const float4*)(ap + 4);
            ra2   = *(const float4*)(ap + 8); ra3   = *(const float4*)(ap + 12);
            rw[0] = *(const float4*)(wp);     rw[1] = *(const float4*)(wp + 4);
            rw2   = *(const float4*)(wp + 8); rw3   = *(const float4*)(wp + 12);
        }
        // MMA on stage c&1
        {
            uint32_t ba = sa + (uint32_t)((c & 1) * PR_STAGE * 2);
            uint32_t bw = sw + (uint32_t)((c & 1) * PR_STAGE * 2);
            #pragma unroll
            for (int s = 0; s < 2; s++) {       // two k16 steps
                uint32_t af[2][4];
                #pragma unroll
                for (int ms = 0; ms < 2; ms++) {
                    uint32_t addr = ba + (uint32_t)((wm + ms * 16 + (lane & 15)) * PRS * 2
                                   + (s * 2 + (lane >> 4)) * 16);
                    ldsm_x4(af[ms][0], af[ms][1], af[ms][2], af[ms][3], addr);
                }
                #pragma unroll
                for (int p = 0; p < 4; p++) {   // n-block pairs
                    uint32_t bf0[2], bf1[2];
                    uint32_t addr = bw + (uint32_t)((wn + p * 16 + (lane & 7) + ((lane & 16) >> 1)) * PRS * 2
                                   + (s * 2 + ((lane >> 3) & 1)) * 16);
                    ldsm_x4(bf0[0], bf0[1], bf1[0], bf1[1], addr);
                    mma_f16(acc[0][2 * p],     af[0], bf0);
                    mma_f16(acc[1][2 * p],     af[1], bf0);
                    mma_f16(acc[0][2 * p + 1], af[0], bf1);
                    mma_f16(acc[1][2 * p + 1], af[1], bf1);
                }
            }
        }
        __syncthreads();
    }

    const int g = lane >> 2;
    const int t = lane & 3;
    #pragma unroll
    for (int j = 0; j < 8; j++) {
        int col = n0 + wn + j * 8 + 2 * t;
        float2 bv = *(const float2*)(bias + col);
        #pragma unroll
        for (int ms = 0; ms < 2; ms++) {
            int r0 = m0 + wm + ms * 16 + g;
            *(float2*)(C + (size_t)r0 * D_ + col) =
                make_float2(acc[ms][j][0] + bv.x, acc[ms][j][1] + bv.y);
            *(float2*)(C + (size_t)(r0 + 8) * D_ + col) =
                make_float2(acc[ms][j][2] + bv.x, acc[ms][j][3] + bv.y);
        }
    }
}

// ============================================================================
// Fused attention: QK^T (fp16 mma) -> online softmax stats -> recompute ->
// write normalized attn -> PV (fp16 mma, P straight from registers).
// CTA = (bh, 128 q rows); warp = 16 q rows x full 128-k tile.
// smem rows: 72 halfs (144B) -> conflict-free LDSM (banks 4m%32 pattern).
// ============================================================================
#define ATS 72                          // halfs per smem row
#define AT_TILE (128 * ATS)             // halfs per tile
#define ATT_SMEM (3 * AT_TILE * 2)      // Q + K + V = 55296 bytes

__global__ __launch_bounds__(256)
void attn_fused(const float* __restrict__ Q, const float* __restrict__ K,
                const float* __restrict__ V, float* __restrict__ attn,
                float* __restrict__ ctx) {
    extern __shared__ __half smh[];
    __half* Qs = smh;
    __half* Ks = smh + AT_TILE;
    __half* Vs = smh + 2 * AT_TILE;
    const uint32_t qsb = smem_u32(Qs);
    const uint32_t ksb = smem_u32(Ks);
    const uint32_t vsb = smem_u32(Vs);

    const int tid = threadIdx.x;
    const int wid = tid >> 5;
    const int lane = tid & 31;
    const int g = lane >> 2;
    const int t = lane & 3;
    const int wq = wid * 16;            // warp's q-row base
    const int qt = blockIdx.x;
    const int bh = blockIdx.y;
    const int b  = bh >> 4;
    const int h  = bh & 15;

    // ---- load Q strip [128][64] -> fp16 smem ----
    {
        const int row = tid >> 1;
        const int ch  = (tid & 1) * 32;
        const float* qp = Q + ((size_t)(b * S_ + qt * 128 + row)) * D_ + h * HD_ + ch;
        #pragma unroll
        for (int q = 0; q < 4; q++) {
            float4 v0 = *(const float4*)(qp + q * 8);
            float4 v1 = *(const float4*)(qp + q * 8 + 4);
            uint4 st = {f2h2(v0.x, v0.y), f2h2(v0.z, v0.w),
                        f2h2(v1.x, v1.y), f2h2(v1.z, v1.w)};
            *(uint4*)((char*)Qs + row * ATS * 2 + ((tid & 1) * 4 + q) * 16) = st;
        }
    }
    __syncthreads();

    // ---- preload Q fragments (4 k16 steps over d=64) ----
    uint32_t qf[4][4];
    #pragma unroll
    for (int s = 0; s < 4; s++) {
        uint32_t addr = qsb + (uint32_t)((wq + (lane & 15)) * ATS * 2
                       + (s * 2 + (lane >> 4)) * 16);
        ldsm_x4(qf[s][0], qf[s][1], qf[s][2], qf[s][3], addr);
    }

    const int krow = tid >> 1;
    const int kch  = (tid & 1) * 32;
    const float* Kp0 = K + ((size_t)(b * S_ + krow)) * D_ + h * HD_ + kch;
    const float* Vp0 = V + ((size_t)(b * S_ + krow)) * D_ + h * HD_ + kch;
    const uint32_t kst = (uint32_t)(krow * ATS * 2 + (kch / 8) * 16);

    float C[16][4];
    float mr[2] = {-1e30f, -1e30f};
    float lr[2] = {0.f, 0.f};

    // ================= pass 1: stats =================
    for (int kt = 0; kt < 8; kt++) {
        __syncthreads();
        {
            const float* kp = Kp0 + (size_t)(kt * 128) * D_;
            #pragma unroll
            for (int q = 0; q < 4; q++) {
                float4 v0 = *(const float4*)(kp + q * 8);
                float4 v1 = *(const float4*)(kp + q * 8 + 4);
                uint4 st = {f2h2(v0.x, v0.y), f2h2(v0.z, v0.w),
                            f2h2(v1.x, v1.y), f2h2(v1.z, v1.w)};
                *(uint4*)((char*)Ks + kst + q * 16) = st;
            }
        }
        __syncthreads();

        #pragma unroll
        for (int j = 0; j < 16; j++)
            #pragma unroll
            for (int e = 0; e < 4; e++) C[j][e] = 0.f;

        #pragma unroll
        for (int s = 0; s < 4; s++) {
            #pragma unroll
            for (int p = 0; p < 8; p++) {
                uint32_t b0[2], b1[2];
                uint32_t addr = ksb + (uint32_t)((p * 16 + (lane & 7) + ((lane & 16) >> 1)) * ATS * 2
                               + (s * 2 + ((lane >> 3) & 1)) * 16);
                ldsm_x4(b0[0], b0[1], b1[0], b1[1], addr);
                mma_f16(C[2 * p],     qf[s], b0);
                mma_f16(C[2 * p + 1], qf[s], b1);
            }
        }

        // online stats (scale 0.125)
        float tm0 = -1e30f, tm1 = -1e30f;
        #pragma unroll
        for (int j = 0; j < 16; j++) {
            tm0 = fmaxf(tm0, fmaxf(C[j][0], C[j][1]));
            tm1 = fmaxf(tm1, fmaxf(C[j][2], C[j][3]));
        }
        tm0 *= 0.125f; tm1 *= 0.125f;
        #pragma unroll
        for (int o = 1; o <= 2; o <<= 1) {
            tm0 = fmaxf(tm0, __shfl_xor_sync(0xffffffffu, tm0, o));
            tm1 = fmaxf(tm1, __shfl_xor_sync(0xffffffffu, tm1, o));
        }
        float n0 = fmaxf(mr[0], tm0), n1 = fmaxf(mr[1], tm1);
        lr[0] *= fast_exp(mr[0] - n0);
        lr[1] *= fast_exp(mr[1] - n1);
        mr[0] = n0; mr[1] = n1;
        #pragma unroll
        for (int j = 0; j < 16; j++) {
            lr[0] += fast_exp(fmaf(C[j][0], 0.125f, -n0))
                   + fast_exp(fmaf(C[j][1], 0.125f, -n0));
            lr[1] += fast_exp(fmaf(C[j][2], 0.125f, -n1))
                   + fast_exp(fmaf(C[j][3], 0.125f, -n1));
        }
    }
    // finalize l across the 4 t-lanes of each row
    #pragma unroll
    for (int o = 1; o <= 2; o <<= 1) {
        lr[0] += __shfl_xor_sync(0xffffffffu, lr[0], o);
        lr[1] += __shfl_xor_sync(0xffffffffu, lr[1], o);
    }
    const float il0 = 1.f / lr[0];
    const float il1 = 1.f / lr[1];

    // ================= pass 2: P write + PV =================
    float pv[8][4];
    #pragma unroll
    for (int n = 0; n < 8; n++)
        #pragma unroll
        for (int e = 0; e < 4; e++) pv[n][e] = 0.f;

    float* arow0 = attn + ((size_t)bh * S_ + qt * 128 + wq + g) * S_;
    float* arow1 = arow0 + (size_t)8 * S_;

    for (int kt = 0; kt < 8; kt++) {
        __syncthreads();
        {
            const float* kp = Kp0 + (size_t)(kt * 128) * D_;
            const float* vp = Vp0 + (size_t)(kt * 128) * D_;
            #pragma unroll
            for (int q = 0; q < 4; q++) {
                float4 v0 = *(const float4*)(kp + q * 8);
                float4 v1 = *(const float4*)(kp + q * 8 + 4);
                uint4 st = {f2h2(v0.x, v0.y), f2h2(v0.z, v0.w),
                            f2h2(v1.x, v1.y), f2h2(v1.z, v1.w)};
                *(uint4*)((char*)Ks + kst + q * 16) = st;
                float4 w0 = *(const float4*)(vp + q * 8);
                float4 w1 = *(const float4*)(vp + q * 8 + 4);
                uint4 sv = {f2h2(w0.x, w0.y), f2h2(w0.z, w0.w),
                            f2h2(w1.x, w1.y), f2h2(w1.z, w1.w)};
                *(uint4*)((char*)Vs + kst + q * 16) = sv;
            }
        }
        __syncthreads();

        #pragma unroll
        for (int j = 0; j < 16; j++)
            #pragma unroll
            for (int e = 0; e < 4; e++) C[j][e] = 0.f;

        #pragma unroll
        for (int s = 0; s < 4; s++) {
            #pragma unroll
            for (int p = 0; p < 8; p++) {
                uint32_t b0[2], b1[2];
                uint32_t addr = ksb + (uint32_t)((p * 16 + (lane & 7) + ((lane & 16) >> 1)) * ATS * 2
                               + (s * 2 + ((lane >> 3) & 1)) * 16);
                ldsm_x4(b0[0], b0[1], b1[0], b1[1], addr);
                mma_f16(C[2 * p],     qf[s], b0);
                mma_f16(C[2 * p + 1], qf[s], b1);
            }
        }

        // P = exp(s - m)/l ; write attn
        #pragma unroll
        for (int j = 0; j < 16; j++) {
            C[j][0] = fast_exp(fmaf(C[j][0], 0.125f, -mr[0])) * il0;
            C[j][1] = fast_exp(fmaf(C[j][1], 0.125f, -mr[0])) * il0;
            C[j][2] = fast_exp(fmaf(C[j][2], 0.125f, -mr[1])) * il1;
            C[j][3] = fast_exp(fmaf(C[j][3], 0.125f, -mr[1])) * il1;
            *(float2*)(arow0 + kt * 128 + j * 8 + 2 * t) = make_float2(C[j][0], C[j][1]);
            *(float2*)(arow1 + kt * 128 + j * 8 + 2 * t) = make_float2(C[j][2], C[j][3]);
        }

        // PV: P fragments straight from registers, V via trans ldmatrix
        #pragma unroll
        for (int s2 = 0; s2 < 8; s2++) {
            uint32_t pa[4];
            pa[0] = f2h2(C[2 * s2][0],     C[2 * s2][1]);
            pa[1] = f2h2(C[2 * s2][2],     C[2 * s2][3]);
            pa[2] = f2h2(C[2 * s2 + 1][0], C[2 * s2 + 1][1]);
            pa[3] = f2h2(C[2 * s2 + 1][2], C[2 * s2 + 1][3]);
            #pragma unroll
            for (int p = 0; p < 4; p++) {
                uint32_t b0[2], b1[2];
                uint32_t addr = vsb + (uint32_t)((s2 * 16 + (lane & 15)) * ATS * 2
                               + (p * 2 + (lane >> 4)) * 16);
                ldsm_x4_t(b0[0], b0[1], b1[0], b1[1], addr);
                mma_f16(pv[2 * p],     pa, b0);
                mma_f16(pv[2 * p + 1], pa, b1);
            }
        }
    }

    // ---- write ctx ----
    float* crow0 = ctx + ((size_t)(b * S_ + qt * 128 + wq + g)) * D_ + h * HD_;
    float* crow1 = crow0 + (size_t)8 * D_;
    #pragma unroll
    for (int n = 0; n < 8; n++) {
        *(float2*)(crow0 + n * 8 + 2 * t) = make_float2(pv[n][0], pv[n][1]);
        *(float2*)(crow1 + n * 8 + 2 * t) = make_float2(pv[n][2], pv[n][3]);
    }
}

// ---------------------------------------------------------------------------
extern "C" void kernel_launch(void* const* d_in, const int* in_sizes, int n_in,
                              void* d_out, int out_size) {
    const float* x  = (const float*)d_in[0];
    const float* Wq = (const float*)d_in[1];
    const float* bq = (const float*)d_in[2];
    const float* Wk = (const float*)d_in[3];
    const float* bk = (const float*)d_in[4];
    const float* Wv = (const float*)d_in[5];
    const float* bv = (const float*)d_in[6];
    const float* Wo = (const float*)d_in[7];
    const float* bo = (const float*)d_in[8];

    float* out = (float*)d_out;
    const size_t OUT_ELEMS = (size_t)B_ * S_ * D_;
    float* attn_ptr = out + OUT_ELEMS;   // (out, attn) concatenated

    float* Qb; cudaGetSymbolAddress((void**)&Qb, g_Q);
    float* Kb; cudaGetSymbolAddress((void**)&Kb, g_K);
    float* Vb; cudaGetSymbolAddress((void**)&Vb, g_V);
    float* Cb; cudaGetSymbolAddress((void**)&Cb, g_C);

    cudaFuncSetAttribute(attn_fused, cudaFuncAttributeMaxDynamicSharedMemorySize,
                         ATT_SMEM);

    // projections (fp16 mma + ldmatrix)
    dim3 gProj(D_ / 128, MROWS / 128);          // (8, 64)
    proj_f16<<<gProj, 256>>>(x, Wq, bq, Qb);
    proj_f16<<<gProj, 256>>>(x, Wk, bk, Kb);
    proj_f16<<<gProj, 256>>>(x, Wv, bv, Vb);

    // fused scores + softmax + attn write + AV
    dim3 gAttn(S_ / 128, B_ * H_);              // (8, 128)
    attn_fused<<<gAttn, 256, ATT_SMEM>>>(Qb, Kb, Vb, attn_ptr, Cb);

    // output projection
    proj_f16<<<gProj, 256>>>(Cb, Wo, bo, out);

    (void)n_in; (void)in_sizes; (void)out_size;
}

// round 11
// speedup vs baseline: 16.7835x; 1.4004x over previous
#include <cuda_runtime.h>
#include <cuda_fp16.h>
#include <cstdint>

// Problem constants
#define B_   8
#define S_   1024
#define D_   1024
#define H_   16
#define HD_  64
#define MROWS (B_ * S_)      // 8192

// ---------------- scratch (static device globals, fp16) ---------------------
__device__ __half g_xh[(size_t)MROWS * D_];
__device__ __half g_Wh[4][(size_t)D_ * D_];
__device__ __half g_Qh[(size_t)MROWS * D_];
__device__ __half g_Kh[(size_t)MROWS * D_];
__device__ __half g_Vh[(size_t)MROWS * D_];
__device__ __half g_Ch[(size_t)MROWS * D_];

// ============================================================================
// Helpers
// ============================================================================
__device__ __forceinline__ uint32_t smem_u32(const void* p) {
    uint32_t a;
    asm("{ .reg .u64 t; cvta.to.shared.u64 t, %1; cvt.u32.u64 %0, t; }"
        : "=r"(a) : "l"(p));
    return a;
}
__device__ __forceinline__ uint32_t f2h2(float lo, float hi) {
    uint32_t r;
    asm("cvt.rn.f16x2.f32 %0, %1, %2;" : "=r"(r) : "f"(hi), "f"(lo));
    return r;
}
__device__ __forceinline__ void ldsm_x4(uint32_t& r0, uint32_t& r1,
                                        uint32_t& r2, uint32_t& r3, uint32_t a) {
    asm volatile("ldmatrix.sync.aligned.m8n8.x4.shared.b16 {%0,%1,%2,%3}, [%4];"
                 : "=r"(r0), "=r"(r1), "=r"(r2), "=r"(r3) : "r"(a));
}
__device__ __forceinline__ void ldsm_x4_t(uint32_t& r0, uint32_t& r1,
                                          uint32_t& r2, uint32_t& r3, uint32_t a) {
    asm volatile("ldmatrix.sync.aligned.m8n8.x4.trans.shared.b16 {%0,%1,%2,%3}, [%4];"
                 : "=r"(r0), "=r"(r1), "=r"(r2), "=r"(r3) : "r"(a));
}
__device__ __forceinline__ void mma_f16(float* c, const uint32_t* a, const uint32_t* b) {
    asm volatile(
        "mma.sync.aligned.m16n8k16.row.col.f32.f16.f16.f32 "
        "{%0,%1,%2,%3}, {%4,%5,%6,%7}, {%8,%9}, {%0,%1,%2,%3};"
        : "+f"(c[0]), "+f"(c[1]), "+f"(c[2]), "+f"(c[3])
        : "r"(a[0]), "r"(a[1]), "r"(a[2]), "r"(a[3]), "r"(b[0]), "r"(b[1]));
}
#define CP16(dst, src) \
    asm volatile("cp.async.cg.shared.global [%0], [%1], 16;" \
                 :: "r"(dst), "l"(src) : "memory")
#define CP_COMMIT() asm volatile("cp.async.commit_group;" ::: "memory")
#define CP_WAIT1()  asm volatile("cp.async.wait_group 1;" ::: "memory")
#define CP_WAIT0()  asm volatile("cp.async.wait_group 0;" ::: "memory")

// fast exp on the FFMA pipe (no MUFU)
__device__ __forceinline__ float fast_exp(float x) {
    x = fminf(fmaxf(x, -80.f), 80.f);
    float y = x * 1.44269504088896341f;
    float nf = rintf(y);
    float f = y - nf;
    float p = 1.33335581e-3f;
    p = fmaf(p, f, 9.61812911e-3f);
    p = fmaf(p, f, 5.55041087e-2f);
    p = fmaf(p, f, 2.40226507e-1f);
    p = fmaf(p, f, 6.93147180e-1f);
    p = fmaf(p, f, 1.0f);
    return p * __int_as_float((127 + (int)nf) << 23);
}

// ============================================================================
// fp32 -> fp16 bulk convert (8 elems/thread)
// ============================================================================
__global__ __launch_bounds__(256)
void f32_to_f16(const float* __restrict__ s, __half* __restrict__ d, int n) {
    int i = (blockIdx.x * 256 + threadIdx.x) * 8;
    if (i < n) {
        float4 a = *(const float4*)(s + i);
        float4 b = *(const float4*)(s + i + 4);
        uint4 o = {f2h2(a.x, a.y), f2h2(a.z, a.w), f2h2(b.x, b.y), f2h2(b.z, b.w)};
        *(uint4*)(d + i) = o;
    }
}

// ============================================================================
// Projection GEMM, fp16 in, cp.async double-buffered, mma.sync m16n8k16.
// C[m,n] = sum_k A[m,k]*W[n,k] + bias[n]. CTA 128x128, BK=32.
// OUT_HALF: write fp16 (scratch) or fp32 (final output).
// ============================================================================
#define PRS 40                         // halfs per smem row
#define PR_STAGE (128 * PRS)           // halfs per operand stage

template <bool OUT_HALF>
__global__ __launch_bounds__(256)
void proj_h(const __half* __restrict__ A, const __half* __restrict__ W,
            const float* __restrict__ bias, void* __restrict__ Cv) {
    __shared__ __half SA[2 * PR_STAGE];
    __shared__ __half SW[2 * PR_STAGE];
    const uint32_t sa = smem_u32(SA);
    const uint32_t sw = smem_u32(SW);

    const int tid = threadIdx.x;
    const int wid = tid >> 5;
    const int lane = tid & 31;
    const int wm = (wid & 3) * 32;
    const int wn = (wid >> 2) * 64;
    const int m0 = blockIdx.y * 128;
    const int n0 = blockIdx.x * 128;

    const int row  = tid >> 1;
    const int part = tid & 1;
    const __half* Ap = A + (size_t)(m0 + row) * D_ + part * 16;
    const __half* Wp = W + (size_t)(n0 + row) * D_ + part * 16;
    const uint32_t sdst = (uint32_t)(row * PRS * 2 + part * 32);

    float acc[2][8][4];
    #pragma unroll
    for (int i = 0; i < 2; i++)
        #pragma unroll
        for (int j = 0; j < 8; j++)
            #pragma unroll
            for (int q = 0; q < 4; q++) acc[i][j][q] = 0.f;

    // prefetch chunk 0 -> stage 0
    {
        CP16(sa + sdst,      Ap);
        CP16(sa + sdst + 16, Ap + 8);
        CP16(sw + sdst,      Wp);
        CP16(sw + sdst + 16, Wp + 8);
        CP_COMMIT();
    }

    for (int c = 0; c < 32; c++) {
        if (c + 1 < 32) {
            uint32_t so = (uint32_t)(((c + 1) & 1) * PR_STAGE * 2);
            const __half* ap = Ap + (c + 1) * 32;
            const __half* wp = Wp + (c + 1) * 32;
            CP16(sa + so + sdst,      ap);
            CP16(sa + so + sdst + 16, ap + 8);
            CP16(sw + so + sdst,      wp);
            CP16(sw + so + sdst + 16, wp + 8);
            CP_COMMIT();
            CP_WAIT1();
        } else {
            CP_WAIT0();
        }
        __syncthreads();
        {
            uint32_t ba = sa + (uint32_t)((c & 1) * PR_STAGE * 2);
            uint32_t bw = sw + (uint32_t)((c & 1) * PR_STAGE * 2);
            #pragma unroll
            for (int s = 0; s < 2; s++) {
                uint32_t af[2][4];
                #pragma unroll
                for (int ms = 0; ms < 2; ms++) {
                    uint32_t addr = ba + (uint32_t)((wm + ms * 16 + (lane & 15)) * PRS * 2
                                   + (s * 2 + (lane >> 4)) * 16);
                    ldsm_x4(af[ms][0], af[ms][1], af[ms][2], af[ms][3], addr);
                }
                #pragma unroll
                for (int p = 0; p < 4; p++) {
                    uint32_t bf0[2], bf1[2];
                    uint32_t addr = bw + (uint32_t)((wn + p * 16 + (lane & 7) + ((lane & 16) >> 1)) * PRS * 2
                                   + (s * 2 + ((lane >> 3) & 1)) * 16);
                    ldsm_x4(bf0[0], bf0[1], bf1[0], bf1[1], addr);
                    mma_f16(acc[0][2 * p],     af[0], bf0);
                    mma_f16(acc[1][2 * p],     af[1], bf0);
                    mma_f16(acc[0][2 * p + 1], af[0], bf1);
                    mma_f16(acc[1][2 * p + 1], af[1], bf1);
                }
            }
        }
        __syncthreads();
    }

    const int g = lane >> 2;
    const int t = lane & 3;
    #pragma unroll
    for (int j = 0; j < 8; j++) {
        int col = n0 + wn + j * 8 + 2 * t;
        float2 bv = *(const float2*)(bias + col);
        #pragma unroll
        for (int ms = 0; ms < 2; ms++) {
            int r0 = m0 + wm + ms * 16 + g;
            if (OUT_HALF) {
                __half* C = (__half*)Cv;
                *(uint32_t*)(C + (size_t)r0 * D_ + col) =
                    f2h2(acc[ms][j][0] + bv.x, acc[ms][j][1] + bv.y);
                *(uint32_t*)(C + (size_t)(r0 + 8) * D_ + col) =
                    f2h2(acc[ms][j][2] + bv.x, acc[ms][j][3] + bv.y);
            } else {
                float* C = (float*)Cv;
                *(float2*)(C + (size_t)r0 * D_ + col) =
                    make_float2(acc[ms][j][0] + bv.x, acc[ms][j][1] + bv.y);
                *(float2*)(C + (size_t)(r0 + 8) * D_ + col) =
                    make_float2(acc[ms][j][2] + bv.x, acc[ms][j][3] + bv.y);
            }
        }
    }
}

// ============================================================================
// Fused attention (fp16 inputs, cp.async double-buffered K/V tiles).
// Pass 1: QK^T -> online (m,l). Pass 2: recompute, write normalized attn,
// PV with P straight from registers. Warp = 16 q rows x full k tile.
// smem: Q[1] K[2] V[2] tiles of 128 rows x ATS halfs.
// ============================================================================
#define ATS 72                          // halfs per smem row
#define AT_TILE (128 * ATS)             // halfs per tile
#define ATT_SMEM (5 * AT_TILE * 2)      // 92160 bytes

__global__ __launch_bounds__(256)
void attn_fused(const __half* __restrict__ Q, const __half* __restrict__ K,
                const __half* __restrict__ V, float* __restrict__ attn,
                __half* __restrict__ ctx) {
    extern __shared__ __half smh[];
    __half* Qs = smh;                       // 1 tile
    const uint32_t qsb = smem_u32(Qs);
    const uint32_t ksb = qsb + AT_TILE * 2;       // K stages 0,1
    const uint32_t vsb = qsb + 3 * AT_TILE * 2;   // V stages 0,1

    const int tid = threadIdx.x;
    const int wid = tid >> 5;
    const int lane = tid & 31;
    const int g = lane >> 2;
    const int t = lane & 3;
    const int wq = wid * 16;
    const int qt = blockIdx.x;
    const int bh = blockIdx.y;
    const int b  = bh >> 4;
    const int h  = bh & 15;

    const int row  = tid >> 1;
    const int part = tid & 1;
    const uint32_t kst = (uint32_t)(row * ATS * 2 + part * 64);

    // ---- load Q strip [128][64] halfs ----
    {
        const __half* qp = Q + ((size_t)(b * S_ + qt * 128 + row)) * D_ + h * HD_ + part * 32;
        *(uint4*)((char*)Qs + kst)      = *(const uint4*)(qp);
        *(uint4*)((char*)Qs + kst + 16) = *(const uint4*)(qp + 8);
        *(uint4*)((char*)Qs + kst + 32) = *(const uint4*)(qp + 16);
        *(uint4*)((char*)Qs + kst + 48) = *(const uint4*)(qp + 24);
    }
    __syncthreads();

    // ---- preload Q fragments ----
    uint32_t qf[4][4];
    #pragma unroll
    for (int s = 0; s < 4; s++) {
        uint32_t addr = qsb + (uint32_t)((wq + (lane & 15)) * ATS * 2
                       + (s * 2 + (lane >> 4)) * 16);
        ldsm_x4(qf[s][0], qf[s][1], qf[s][2], qf[s][3], addr);
    }

    const __half* Kp0 = K + ((size_t)(b * S_ + row)) * D_ + h * HD_ + part * 32;
    const __half* Vp0 = V + ((size_t)(b * S_ + row)) * D_ + h * HD_ + part * 32;

    float C[16][4];
    float mr[2] = {-1e30f, -1e30f};
    float lr[2] = {0.f, 0.f};

    // ================= pass 1: stats (K only) =================
    {
        const __half* kp = Kp0;
        CP16(ksb + kst,      kp);       CP16(ksb + kst + 16, kp + 8);
        CP16(ksb + kst + 32, kp + 16);  CP16(ksb + kst + 48, kp + 24);
        CP_COMMIT();
    }
    for (int kt = 0; kt < 8; kt++) {
        if (kt + 1 < 8) {
            uint32_t so = (uint32_t)(((kt + 1) & 1) * AT_TILE * 2);
            const __half* kp = Kp0 + (size_t)((kt + 1) * 128) * D_;
            CP16(ksb + so + kst,      kp);       CP16(ksb + so + kst + 16, kp + 8);
            CP16(ksb + so + kst + 32, kp + 16);  CP16(ksb + so + kst + 48, kp + 24);
            CP_COMMIT();
            CP_WAIT1();
        } else {
            CP_WAIT0();
        }
        __syncthreads();

        #pragma unroll
        for (int j = 0; j < 16; j++)
            #pragma unroll
            for (int e = 0; e < 4; e++) C[j][e] = 0.f;

        uint32_t kb = ksb + (uint32_t)((kt & 1) * AT_TILE * 2);
        #pragma unroll
        for (int s = 0; s < 4; s++) {
            #pragma unroll
            for (int p = 0; p < 8; p++) {
                uint32_t b0[2], b1[2];
                uint32_t addr = kb + (uint32_t)((p * 16 + (lane & 7) + ((lane & 16) >> 1)) * ATS * 2
                               + (s * 2 + ((lane >> 3) & 1)) * 16);
                ldsm_x4(b0[0], b0[1], b1[0], b1[1], addr);
                mma_f16(C[2 * p],     qf[s], b0);
                mma_f16(C[2 * p + 1], qf[s], b1);
            }
        }
        __syncthreads();

        float tm0 = -1e30f, tm1 = -1e30f;
        #pragma unroll
        for (int j = 0; j < 16; j++) {
            tm0 = fmaxf(tm0, fmaxf(C[j][0], C[j][1]));
            tm1 = fmaxf(tm1, fmaxf(C[j][2], C[j][3]));
        }
        tm0 *= 0.125f; tm1 *= 0.125f;
        #pragma unroll
        for (int o = 1; o <= 2; o <<= 1) {
            tm0 = fmaxf(tm0, __shfl_xor_sync(0xffffffffu, tm0, o));
            tm1 = fmaxf(tm1, __shfl_xor_sync(0xffffffffu, tm1, o));
        }
        float n0 = fmaxf(mr[0], tm0), n1 = fmaxf(mr[1], tm1);
        lr[0] *= fast_exp(mr[0] - n0);
        lr[1] *= fast_exp(mr[1] - n1);
        mr[0] = n0; mr[1] = n1;
        #pragma unroll
        for (int j = 0; j < 16; j++) {
            lr[0] += fast_exp(fmaf(C[j][0], 0.125f, -n0))
                   + fast_exp(fmaf(C[j][1], 0.125f, -n0));
            lr[1] += fast_exp(fmaf(C[j][2], 0.125f, -n1))
                   + fast_exp(fmaf(C[j][3], 0.125f, -n1));
        }
    }
    #pragma unroll
    for (int o = 1; o <= 2; o <<= 1) {
        lr[0] += __shfl_xor_sync(0xffffffffu, lr[0], o);
        lr[1] += __shfl_xor_sync(0xffffffffu, lr[1], o);
    }
    const float il0 = 1.f / lr[0];
    const float il1 = 1.f / lr[1];

    // ================= pass 2: P write + PV (K + V) =================
    float pv[8][4];
    #pragma unroll
    for (int n = 0; n < 8; n++)
        #pragma unroll
        for (int e = 0; e < 4; e++) pv[n][e] = 0.f;

    float* arow0 = attn + ((size_t)bh * S_ + qt * 128 + wq + g) * S_;
    float* arow1 = arow0 + (size_t)8 * S_;

    {
        const __half* kp = Kp0;
        const __half* vp = Vp0;
        CP16(ksb + kst,      kp);       CP16(ksb + kst + 16, kp + 8);
        CP16(ksb + kst + 32, kp + 16);  CP16(ksb + kst + 48, kp + 24);
        CP16(vsb + kst,      vp);       CP16(vsb + kst + 16, vp + 8);
        CP16(vsb + kst + 32, vp + 16);  CP16(vsb + kst + 48, vp + 24);
        CP_COMMIT();
    }
    for (int kt = 0; kt < 8; kt++) {
        if (kt + 1 < 8) {
            uint32_t so = (uint32_t)(((kt + 1) & 1) * AT_TILE * 2);
            const __half* kp = Kp0 + (size_t)((kt + 1) * 128) * D_;
            const __half* vp = Vp0 + (size_t)((kt + 1) * 128) * D_;
            CP16(ksb + so + kst,      kp);       CP16(ksb + so + kst + 16, kp + 8);
            CP16(ksb + so + kst + 32, kp + 16);  CP16(ksb + so + kst + 48, kp + 24);
            CP16(vsb + so + kst,      vp);       CP16(vsb + so + kst + 16, vp + 8);
            CP16(vsb + so + kst + 32, vp + 16);  CP16(vsb + so + kst + 48, vp + 24);
            CP_COMMIT();
            CP_WAIT1();
        } else {
            CP_WAIT0();
        }
        __syncthreads();

        #pragma unroll
        for (int j = 0; j < 16; j++)
            #pragma unroll
            for (int e = 0; e < 4; e++) C[j][e] = 0.f;

        uint32_t kb = ksb + (uint32_t)((kt & 1) * AT_TILE * 2);
        uint32_t vb = vsb + (uint32_t)((kt & 1) * AT_TILE * 2);
        #pragma unroll
        for (int s = 0; s < 4; s++) {
            #pragma unroll
            for (int p = 0; p < 8; p++) {
                uint32_t b0[2], b1[2];
                uint32_t addr = kb + (uint32_t)((p * 16 + (lane & 7) + ((lane & 16) >> 1)) * ATS * 2
                               + (s * 2 + ((lane >> 3) & 1)) * 16);
                ldsm_x4(b0[0], b0[1], b1[0], b1[1], addr);
                mma_f16(C[2 * p],     qf[s], b0);
                mma_f16(C[2 * p + 1], qf[s], b1);
            }
        }

        #pragma unroll
        for (int j = 0; j < 16; j++) {
            C[j][0] = fast_exp(fmaf(C[j][0], 0.125f, -mr[0])) * il0;
            C[j][1] = fast_exp(fmaf(C[j][1], 0.125f, -mr[0])) * il0;
            C[j][2] = fast_exp(fmaf(C[j][2], 0.125f, -mr[1])) * il1;
            C[j][3] = fast_exp(fmaf(C[j][3], 0.125f, -mr[1])) * il1;
            *(float2*)(arow0 + kt * 128 + j * 8 + 2 * t) = make_float2(C[j][0], C[j][1]);
            *(float2*)(arow1 + kt * 128 + j * 8 + 2 * t) = make_float2(C[j][2], C[j][3]);
        }

        #pragma unroll
        for (int s2 = 0; s2 < 8; s2++) {
            uint32_t pa[4];
            pa[0] = f2h2(C[2 * s2][0],     C[2 * s2][1]);
            pa[1] = f2h2(C[2 * s2][2],     C[2 * s2][3]);
            pa[2] = f2h2(C[2 * s2 + 1][0], C[2 * s2 + 1][1]);
            pa[3] = f2h2(C[2 * s2 + 1][2], C[2 * s2 + 1][3]);
            #pragma unroll
            for (int p = 0; p < 4; p++) {
                uint32_t b0[2], b1[2];
                uint32_t addr = vb + (uint32_t)((s2 * 16 + (lane & 15)) * ATS * 2
                               + (p * 2 + (lane >> 4)) * 16);
                ldsm_x4_t(b0[0], b0[1], b1[0], b1[1], addr);
                mma_f16(pv[2 * p],     pa, b0);
                mma_f16(pv[2 * p + 1], pa, b1);
            }
        }
        __syncthreads();
    }

    // ---- write ctx (fp16) ----
    __half* crow0 = ctx + ((size_t)(b * S_ + qt * 128 + wq + g)) * D_ + h * HD_;
    __half* crow1 = crow0 + (size_t)8 * D_;
    #pragma unroll
    for (int n = 0; n < 8; n++) {
        *(uint32_t*)(crow0 + n * 8 + 2 * t) = f2h2(pv[n][0], pv[n][1]);
        *(uint32_t*)(crow1 + n * 8 + 2 * t) = f2h2(pv[n][2], pv[n][3]);
    }
}

// ---------------------------------------------------------------------------
extern "C" void kernel_launch(void* const* d_in, const int* in_sizes, int n_in,
                              void* d_out, int out_size) {
    const float* x  = (const float*)d_in[0];
    const float* Wq = (const float*)d_in[1];
    const float* bq = (const float*)d_in[2];
    const float* Wk = (const float*)d_in[3];
    const float* bk = (const float*)d_in[4];
    const float* Wv = (const float*)d_in[5];
    const float* bv = (const float*)d_in[6];
    const float* Wo = (const float*)d_in[7];
    const float* bo = (const float*)d_in[8];

    float* out = (float*)d_out;
    const size_t OUT_ELEMS = (size_t)B_ * S_ * D_;
    float* attn_ptr = out + OUT_ELEMS;   // (out, attn) concatenated

    __half* xh; cudaGetSymbolAddress((void**)&xh, g_xh);
    __half* Wh; cudaGetSymbolAddress((void**)&Wh, g_Wh);
    __half* Qh; cudaGetSymbolAddress((void**)&Qh, g_Qh);
    __half* Kh; cudaGetSymbolAddress((void**)&Kh, g_Kh);
    __half* Vh; cudaGetSymbolAddress((void**)&Vh, g_Vh);
    __half* Ch; cudaGetSymbolAddress((void**)&Ch, g_Ch);
    __half* Wh0 = Wh;
    __half* Wh1 = Wh + (size_t)D_ * D_;
    __half* Wh2 = Wh + 2 * (size_t)D_ * D_;
    __half* Wh3 = Wh + 3 * (size_t)D_ * D_;

    cudaFuncSetAttribute(attn_fused, cudaFuncAttributeMaxDynamicSharedMemorySize,
                         ATT_SMEM);

    // convert inputs to fp16
    const int NX = MROWS * D_;       // 8388608
    const int NW = D_ * D_;          // 1048576
    f32_to_f16<<<NX / 8 / 256, 256>>>(x,  xh,  NX);
    f32_to_f16<<<NW / 8 / 256, 256>>>(Wq, Wh0, NW);
    f32_to_f16<<<NW / 8 / 256, 256>>>(Wk, Wh1, NW);
    f32_to_f16<<<NW / 8 / 256, 256>>>(Wv, Wh2, NW);
    f32_to_f16<<<NW / 8 / 256, 256>>>(Wo, Wh3, NW);

    // projections (fp16 in/out)
    dim3 gProj(D_ / 128, MROWS / 128);          // (8, 64)
    proj_h<true><<<gProj, 256>>>(xh, Wh0, bq, Qh);
    proj_h<true><<<gProj, 256>>>(xh, Wh1, bk, Kh);
    proj_h<true><<<gProj, 256>>>(xh, Wh2, bv, Vh);

    // fused scores + softmax + attn write + AV
    dim3 gAttn(S_ / 128, B_ * H_);              // (8, 128)
    attn_fused<<<gAttn, 256, ATT_SMEM>>>(Qh, Kh, Vh, attn_ptr, Ch);

    // output projection (fp16 in, fp32 out)
    proj_h<false><<<gProj, 256>>>(Ch, Wh3, bo, out);

    (void)n_in; (void)in_sizes; (void)out_size;
}

// round 16
// speedup vs baseline: 17.3962x; 1.0365x over previous
#include <cuda_runtime.h>
#include <cuda_fp16.h>
#include <cstdint>

// Problem constants
#define B_   8
#define S_   1024
#define D_   1024
#define H_   16
#define HD_  64
#define MROWS (B_ * S_)      // 8192

// ---------------- scratch (static device globals, fp16) ---------------------
__device__ __half g_xh[(size_t)MROWS * D_];
__device__ __half g_Wh[4][(size_t)D_ * D_];
__device__ __half g_Qh[(size_t)MROWS * D_];
__device__ __half g_Kh[(size_t)MROWS * D_];
__device__ __half g_Vh[(size_t)MROWS * D_];
__device__ __half g_Ch[(size_t)MROWS * D_];

// ============================================================================
// Helpers
// ============================================================================
__device__ __forceinline__ uint32_t smem_u32(const void* p) {
    uint32_t a;
    asm("{ .reg .u64 t; cvta.to.shared.u64 t, %1; cvt.u32.u64 %0, t; }"
        : "=r"(a) : "l"(p));
    return a;
}
__device__ __forceinline__ uint32_t f2h2(float lo, float hi) {
    uint32_t r;
    asm("cvt.rn.f16x2.f32 %0, %1, %2;" : "=r"(r) : "f"(hi), "f"(lo));
    return r;
}
__device__ __forceinline__ void ldsm_x4(uint32_t& r0, uint32_t& r1,
                                        uint32_t& r2, uint32_t& r3, uint32_t a) {
    asm volatile("ldmatrix.sync.aligned.m8n8.x4.shared.b16 {%0,%1,%2,%3}, [%4];"
                 : "=r"(r0), "=r"(r1), "=r"(r2), "=r"(r3) : "r"(a));
}
__device__ __forceinline__ void ldsm_x4_t(uint32_t& r0, uint32_t& r1,
                                          uint32_t& r2, uint32_t& r3, uint32_t a) {
    asm volatile("ldmatrix.sync.aligned.m8n8.x4.trans.shared.b16 {%0,%1,%2,%3}, [%4];"
                 : "=r"(r0), "=r"(r1), "=r"(r2), "=r"(r3) : "r"(a));
}
__device__ __forceinline__ void mma_f16(float* c, const uint32_t* a, const uint32_t* b) {
    asm volatile(
        "mma.sync.aligned.m16n8k16.row.col.f32.f16.f16.f32 "
        "{%0,%1,%2,%3}, {%4,%5,%6,%7}, {%8,%9}, {%0,%1,%2,%3};"
        : "+f"(c[0]), "+f"(c[1]), "+f"(c[2]), "+f"(c[3])
        : "r"(a[0]), "r"(a[1]), "r"(a[2]), "r"(a[3]), "r"(b[0]), "r"(b[1]));
}
#define CP16(dst, src) \
    asm volatile("cp.async.cg.shared.global [%0], [%1], 16;" \
                 :: "r"(dst), "l"(src) : "memory")
#define CP_COMMIT() asm volatile("cp.async.commit_group;" ::: "memory")
#define CP_WAIT1()  asm volatile("cp.async.wait_group 1;" ::: "memory")
#define CP_WAIT0()  asm volatile("cp.async.wait_group 0;" ::: "memory")

// fast exp on the FFMA pipe (no MUFU)
__device__ __forceinline__ float fast_exp(float x) {
    x = fminf(fmaxf(x, -80.f), 80.f);
    float y = x * 1.44269504088896341f;
    float nf = rintf(y);
    float f = y - nf;
    float p = 1.33335581e-3f;
    p = fmaf(p, f, 9.61812911e-3f);
    p = fmaf(p, f, 5.55041087e-2f);
    p = fmaf(p, f, 2.40226507e-1f);
    p = fmaf(p, f, 6.93147180e-1f);
    p = fmaf(p, f, 1.0f);
    return p * __int_as_float((127 + (int)nf) << 23);
}

// ============================================================================
// fp32 -> fp16 bulk convert (8 elems/thread)
// ============================================================================
__global__ __launch_bounds__(256)
void f32_to_f16(const float* __restrict__ s, __half* __restrict__ d, int n) {
    int i = (blockIdx.x * 256 + threadIdx.x) * 8;
    if (i < n) {
        float4 a = *(const float4*)(s + i);
        float4 b = *(const float4*)(s + i + 4);
        uint4 o = {f2h2(a.x, a.y), f2h2(a.z, a.w), f2h2(b.x, b.y), f2h2(b.z, b.w)};
        *(uint4*)(d + i) = o;
    }
}

// ============================================================================
// Projection GEMM, fp16 in, cp.async double-buffered, mma.sync m16n8k16.
// C[m,n] = sum_k A[m,k]*W[n,k] + bias[n]. CTA 128x128, BK=32, 2 CTAs/SM.
// ============================================================================
#define PRS 40                         // halfs per smem row
#define PR_STAGE (128 * PRS)           // halfs per operand stage

template <bool OUT_HALF>
__global__ __launch_bounds__(256, 2)
void proj_h(const __half* __restrict__ A, const __half* __restrict__ W,
            const float* __restrict__ bias, void* __restrict__ Cv) {
    __shared__ __half SA[2 * PR_STAGE];
    __shared__ __half SW[2 * PR_STAGE];
    const uint32_t sa = smem_u32(SA);
    const uint32_t sw = smem_u32(SW);

    const int tid = threadIdx.x;
    const int wid = tid >> 5;
    const int lane = tid & 31;
    const int wm = (wid & 3) * 32;
    const int wn = (wid >> 2) * 64;
    const int m0 = blockIdx.y * 128;
    const int n0 = blockIdx.x * 128;

    const int row  = tid >> 1;
    const int part = tid & 1;
    const __half* Ap = A + (size_t)(m0 + row) * D_ + part * 16;
    const __half* Wp = W + (size_t)(n0 + row) * D_ + part * 16;
    const uint32_t sdst = (uint32_t)(row * PRS * 2 + part * 32);

    float acc[2][8][4];
    #pragma unroll
    for (int i = 0; i < 2; i++)
        #pragma unroll
        for (int j = 0; j < 8; j++)
            #pragma unroll
            for (int q = 0; q < 4; q++) acc[i][j][q] = 0.f;

    // prefetch chunk 0 -> stage 0
    {
        CP16(sa + sdst,      Ap);
        CP16(sa + sdst + 16, Ap + 8);
        CP16(sw + sdst,      Wp);
        CP16(sw + sdst + 16, Wp + 8);
        CP_COMMIT();
    }

    for (int c = 0; c < 32; c++) {
        if (c + 1 < 32) {
            uint32_t so = (uint32_t)(((c + 1) & 1) * PR_STAGE * 2);
            const __half* ap = Ap + (c + 1) * 32;
            const __half* wp = Wp + (c + 1) * 32;
            CP16(sa + so + sdst,      ap);
            CP16(sa + so + sdst + 16, ap + 8);
            CP16(sw + so + sdst,      wp);
            CP16(sw + so + sdst + 16, wp + 8);
            CP_COMMIT();
            CP_WAIT1();
        } else {
            CP_WAIT0();
        }
        __syncthreads();
        {
            uint32_t ba = sa + (uint32_t)((c & 1) * PR_STAGE * 2);
            uint32_t bw = sw + (uint32_t)((c & 1) * PR_STAGE * 2);
            #pragma unroll
            for (int s = 0; s < 2; s++) {
                uint32_t af[2][4];
                #pragma unroll
                for (int ms = 0; ms < 2; ms++) {
                    uint32_t addr = ba + (uint32_t)((wm + ms * 16 + (lane & 15)) * PRS * 2
                                   + (s * 2 + (lane >> 4)) * 16);
                    ldsm_x4(af[ms][0], af[ms][1], af[ms][2], af[ms][3], addr);
                }
                #pragma unroll
                for (int p = 0; p < 4; p++) {
                    uint32_t bf0[2], bf1[2];
                    uint32_t addr = bw + (uint32_t)((wn + p * 16 + (lane & 7) + ((lane & 16) >> 1)) * PRS * 2
                                   + (s * 2 + ((lane >> 3) & 1)) * 16);
                    ldsm_x4(bf0[0], bf0[1], bf1[0], bf1[1], addr);
                    mma_f16(acc[0][2 * p],     af[0], bf0);
                    mma_f16(acc[1][2 * p],     af[1], bf0);
                    mma_f16(acc[0][2 * p + 1], af[0], bf1);
                    mma_f16(acc[1][2 * p + 1], af[1], bf1);
                }
            }
        }
        __syncthreads();
    }

    const int g = lane >> 2;
    const int t = lane & 3;
    #pragma unroll
    for (int j = 0; j < 8; j++) {
        int col = n0 + wn + j * 8 + 2 * t;
        float2 bv = *(const float2*)(bias + col);
        #pragma unroll
        for (int ms = 0; ms < 2; ms++) {
            int r0 = m0 + wm + ms * 16 + g;
            if (OUT_HALF) {
                __half* C = (__half*)Cv;
                *(uint32_t*)(C + (size_t)r0 * D_ + col) =
                    f2h2(acc[ms][j][0] + bv.x, acc[ms][j][1] + bv.y);
                *(uint32_t*)(C + (size_t)(r0 + 8) * D_ + col) =
                    f2h2(acc[ms][j][2] + bv.x, acc[ms][j][3] + bv.y);
            } else {
                float* C = (float*)Cv;
                *(float2*)(C + (size_t)r0 * D_ + col) =
                    make_float2(acc[ms][j][0] + bv.x, acc[ms][j][1] + bv.y);
                *(float2*)(C + (size_t)(r0 + 8) * D_ + col) =
                    make_float2(acc[ms][j][2] + bv.x, acc[ms][j][3] + bv.y);
            }
        }
    }
}

// ============================================================================
// Fused attention v2 (score-stash):
// Pass 1: QK^T (fp16 mma) -> write RAW scaled scores to attn + online (m,l).
// Pass 2: read scores back (L2-hot), normalize in place, PV from registers.
// No QK^T recompute. smem: Q tile + 2 staging tiles (K in p1, V in p2).
// ============================================================================
#define ATS 72                          // halfs per smem row
#define AT_TILE (128 * ATS)             // halfs per tile
#define ATT_SMEM (3 * AT_TILE * 2)      // Q + 2 staging = 55296 bytes

__global__ __launch_bounds__(256)
void attn_fused(const __half* __restrict__ Q, const __half* __restrict__ K,
                const __half* __restrict__ V, float* __restrict__ attn,
                __half* __restrict__ ctx) {
    extern __shared__ __half smh[];
    const uint32_t qsb = smem_u32(smh);
    const uint32_t stg = qsb + AT_TILE * 2;   // staging stage 0; stage 1 at +AT_TILE*2

    const int tid = threadIdx.x;
    const int wid = tid >> 5;
    const int lane = tid & 31;
    const int g = lane >> 2;
    const int t = lane & 3;
    const int wq = wid * 16;
    const int qt = blockIdx.x;
    const int bh = blockIdx.y;
    const int b  = bh >> 4;
    const int h  = bh & 15;

    const int row  = tid >> 1;
    const int part = tid & 1;
    const uint32_t kst = (uint32_t)(row * ATS * 2 + part * 64);

    // ---- load Q strip [128][64] halfs ----
    {
        const __half* qp = Q + ((size_t)(b * S_ + qt * 128 + row)) * D_ + h * HD_ + part * 32;
        *(uint4*)((char*)smh + kst)      = *(const uint4*)(qp);
        *(uint4*)((char*)smh + kst + 16) = *(const uint4*)(qp + 8);
        *(uint4*)((char*)smh + kst + 32) = *(const uint4*)(qp + 16);
        *(uint4*)((char*)smh + kst + 48) = *(const uint4*)(qp + 24);
    }
    __syncthreads();

    // ---- preload Q fragments ----
    uint32_t qf[4][4];
    #pragma unroll
    for (int s = 0; s < 4; s++) {
        uint32_t addr = qsb + (uint32_t)((wq + (lane & 15)) * ATS * 2
                       + (s * 2 + (lane >> 4)) * 16);
        ldsm_x4(qf[s][0], qf[s][1], qf[s][2], qf[s][3], addr);
    }

    const __half* Kp0 = K + ((size_t)(b * S_ + row)) * D_ + h * HD_ + part * 32;
    const __half* Vp0 = V + ((size_t)(b * S_ + row)) * D_ + h * HD_ + part * 32;

    float C[16][4];
    float mr[2] = {-1e30f, -1e30f};
    float lr[2] = {0.f, 0.f};

    float* arow0 = attn + ((size_t)bh * S_ + qt * 128 + wq + g) * S_;
    float* arow1 = arow0 + (size_t)8 * S_;

    // ================= pass 1: QK^T -> raw scores + stats =================
    {
        const __half* kp = Kp0;
        CP16(stg + kst,      kp);       CP16(stg + kst + 16, kp + 8);
        CP16(stg + kst + 32, kp + 16);  CP16(stg + kst + 48, kp + 24);
        CP_COMMIT();
    }
    for (int kt = 0; kt < 8; kt++) {
        if (kt + 1 < 8) {
            uint32_t so = stg + (uint32_t)(((kt + 1) & 1) * AT_TILE * 2);
            const __half* kp = Kp0 + (size_t)((kt + 1) * 128) * D_;
            CP16(so + kst,      kp);       CP16(so + kst + 16, kp + 8);
            CP16(so + kst + 32, kp + 16);  CP16(so + kst + 48, kp + 24);
            CP_COMMIT();
            CP_WAIT1();
        } else {
            CP_WAIT0();
        }
        __syncthreads();

        #pragma unroll
        for (int j = 0; j < 16; j++)
            #pragma unroll
            for (int e = 0; e < 4; e++) C[j][e] = 0.f;

        uint32_t kb = stg + (uint32_t)((kt & 1) * AT_TILE * 2);
        #pragma unroll
        for (int s = 0; s < 4; s++) {
            #pragma unroll
            for (int p = 0; p < 8; p++) {
                uint32_t b0[2], b1[2];
                uint32_t addr = kb + (uint32_t)((p * 16 + (lane & 7) + ((lane & 16) >> 1)) * ATS * 2
                               + (s * 2 + ((lane >> 3) & 1)) * 16);
                ldsm_x4(b0[0], b0[1], b1[0], b1[1], addr);
                mma_f16(C[2 * p],     qf[s], b0);
                mma_f16(C[2 * p + 1], qf[s], b1);
            }
        }
        __syncthreads();

        // scale, store raw scores, update stats
        float tm0 = -1e30f, tm1 = -1e30f;
        #pragma unroll
        for (int j = 0; j < 16; j++) {
            C[j][0] *= 0.125f; C[j][1] *= 0.125f;
            C[j][2] *= 0.125f; C[j][3] *= 0.125f;
            *(float2*)(arow0 + kt * 128 + j * 8 + 2 * t) = make_float2(C[j][0], C[j][1]);
            *(float2*)(arow1 + kt * 128 + j * 8 + 2 * t) = make_float2(C[j][2], C[j][3]);
            tm0 = fmaxf(tm0, fmaxf(C[j][0], C[j][1]));
            tm1 = fmaxf(tm1, fmaxf(C[j][2], C[j][3]));
        }
        #pragma unroll
        for (int o = 1; o <= 2; o <<= 1) {
            tm0 = fmaxf(tm0, __shfl_xor_sync(0xffffffffu, tm0, o));
            tm1 = fmaxf(tm1, __shfl_xor_sync(0xffffffffu, tm1, o));
        }
        float n0 = fmaxf(mr[0], tm0), n1 = fmaxf(mr[1], tm1);
        lr[0] *= fast_exp(mr[0] - n0);
        lr[1] *= fast_exp(mr[1] - n1);
        mr[0] = n0; mr[1] = n1;
        #pragma unroll
        for (int j = 0; j < 16; j++) {
            lr[0] += fast_exp(C[j][0] - n0) + fast_exp(C[j][1] - n0);
            lr[1] += fast_exp(C[j][2] - n1) + fast_exp(C[j][3] - n1);
        }
    }
    #pragma unroll
    for (int o = 1; o <= 2; o <<= 1) {
        lr[0] += __shfl_xor_sync(0xffffffffu, lr[0], o);
        lr[1] += __shfl_xor_sync(0xffffffffu, lr[1], o);
    }
    const float il0 = 1.f / lr[0];
    const float il1 = 1.f / lr[1];

    // ================= pass 2: read scores, normalize, PV =================
    float pv[8][4];
    #pragma unroll
    for (int n = 0; n < 8; n++)
        #pragma unroll
        for (int e = 0; e < 4; e++) pv[n][e] = 0.f;

    {
        const __half* vp = Vp0;
        CP16(stg + kst,      vp);       CP16(stg + kst + 16, vp + 8);
        CP16(stg + kst + 32, vp + 16);  CP16(stg + kst + 48, vp + 24);
        CP_COMMIT();
    }
    for (int kt = 0; kt < 8; kt++) {
        if (kt + 1 < 8) {
            uint32_t so = stg + (uint32_t)(((kt + 1) & 1) * AT_TILE * 2);
            const __half* vp = Vp0 + (size_t)((kt + 1) * 128) * D_;
            CP16(so + kst,      vp);       CP16(so + kst + 16, vp + 8);
            CP16(so + kst + 32, vp + 16);  CP16(so + kst + 48, vp + 24);
            CP_COMMIT();
            CP_WAIT1();
        } else {
            CP_WAIT0();
        }
        __syncthreads();

        // read raw scores back (L2-hot), normalize, write final attn
        #pragma unroll
        for (int j = 0; j < 16; j++) {
            float2 a0 = *(const float2*)(arow0 + kt * 128 + j * 8 + 2 * t);
            float2 a1 = *(const float2*)(arow1 + kt * 128 + j * 8 + 2 * t);
            C[j][0] = fast_exp(a0.x - mr[0]) * il0;
            C[j][1] = fast_exp(a0.y - mr[0]) * il0;
            C[j][2] = fast_exp(a1.x - mr[1]) * il1;
            C[j][3] = fast_exp(a1.y - mr[1]) * il1;
            *(float2*)(arow0 + kt * 128 + j * 8 + 2 * t) = make_float2(C[j][0], C[j][1]);
            *(float2*)(arow1 + kt * 128 + j * 8 + 2 * t) = make_float2(C[j][2], C[j][3]);
        }

        // PV: P fragments from registers, V via trans ldmatrix
        uint32_t vb = stg + (uint32_t)((kt & 1) * AT_TILE * 2);
        #pragma unroll
        for (int s2 = 0; s2 < 8; s2++) {
            uint32_t pa[4];
            pa[0] = f2h2(C[2 * s2][0],     C[2 * s2][1]);
            pa[1] = f2h2(C[2 * s2][2],     C[2 * s2][3]);
            pa[2] = f2h2(C[2 * s2 + 1][0], C[2 * s2 + 1][1]);
            pa[3] = f2h2(C[2 * s2 + 1][2], C[2 * s2 + 1][3]);
            #pragma unroll
            for (int p = 0; p < 4; p++) {
                uint32_t b0[2], b1[2];
                uint32_t addr = vb + (uint32_t)((s2 * 16 + (lane & 15)) * ATS * 2
                               + (p * 2 + (lane >> 4)) * 16);
                ldsm_x4_t(b0[0], b0[1], b1[0], b1[1], addr);
                mma_f16(pv[2 * p],     pa, b0);
                mma_f16(pv[2 * p + 1], pa, b1);
            }
        }
        __syncthreads();
    }

    // ---- write ctx (fp16) ----
    __half* crow0 = ctx + ((size_t)(b * S_ + qt * 128 + wq + g)) * D_ + h * HD_;
    __half* crow1 = crow0 + (size_t)8 * D_;
    #pragma unroll
    for (int n = 0; n < 8; n++) {
        *(uint32_t*)(crow0 + n * 8 + 2 * t) = f2h2(pv[n][0], pv[n][1]);
        *(uint32_t*)(crow1 + n * 8 + 2 * t) = f2h2(pv[n][2], pv[n][3]);
    }
}

// ---------------------------------------------------------------------------
extern "C" void kernel_launch(void* const* d_in, const int* in_sizes, int n_in,
                              void* d_out, int out_size) {
    const float* x  = (const float*)d_in[0];
    const float* Wq = (const float*)d_in[1];
    const float* bq = (const float*)d_in[2];
    const float* Wk = (const float*)d_in[3];
    const float* bk = (const float*)d_in[4];
    const float* Wv = (const float*)d_in[5];
    const float* bv = (const float*)d_in[6];
    const float* Wo = (const float*)d_in[7];
    const float* bo = (const float*)d_in[8];

    float* out = (float*)d_out;
    const size_t OUT_ELEMS = (size_t)B_ * S_ * D_;
    float* attn_ptr = out + OUT_ELEMS;   // (out, attn) concatenated

    __half* xh; cudaGetSymbolAddress((void**)&xh, g_xh);
    __half* Wh; cudaGetSymbolAddress((void**)&Wh, g_Wh);
    __half* Qh; cudaGetSymbolAddress((void**)&Qh, g_Qh);
    __half* Kh; cudaGetSymbolAddress((void**)&Kh, g_Kh);
    __half* Vh; cudaGetSymbolAddress((void**)&Vh, g_Vh);
    __half* Ch; cudaGetSymbolAddress((void**)&Ch, g_Ch);
    __half* Wh0 = Wh;
    __half* Wh1 = Wh + (size_t)D_ * D_;
    __half* Wh2 = Wh + 2 * (size_t)D_ * D_;
    __half* Wh3 = Wh + 3 * (size_t)D_ * D_;

    cudaFuncSetAttribute(attn_fused, cudaFuncAttributeMaxDynamicSharedMemorySize,
                         ATT_SMEM);

    // convert inputs to fp16
    const int NX = MROWS * D_;       // 8388608
    const int NW = D_ * D_;          // 1048576
    f32_to_f16<<<NX / 8 / 256, 256>>>(x,  xh,  NX);
    f32_to_f16<<<NW / 8 / 256, 256>>>(Wq, Wh0, NW);
    f32_to_f16<<<NW / 8 / 256, 256>>>(Wk, Wh1, NW);
    f32_to_f16<<<NW / 8 / 256, 256>>>(Wv, Wh2, NW);
    f32_to_f16<<<NW / 8 / 256, 256>>>(Wo, Wh3, NW);

    // projections (fp16 in/out, 2 CTAs/SM)
    dim3 gProj(D_ / 128, MROWS / 128);          // (8, 64)
    proj_h<true><<<gProj, 256>>>(xh, Wh0, bq, Qh);
    proj_h<true><<<gProj, 256>>>(xh, Wh1, bk, Kh);
    proj_h<true><<<gProj, 256>>>(xh, Wh2, bv, Vh);

    // fused scores + softmax + attn write + AV (score-stash)
    dim3 gAttn(S_ / 128, B_ * H_);              // (8, 128)
    attn_fused<<<gAttn, 256, ATT_SMEM>>>(Qh, Kh, Vh, attn_ptr, Ch);

    // output projection (fp16 in, fp32 out)
    proj_h<false><<<gProj, 256>>>(Ch, Wh3, bo, out);

    (void)n_in; (void)in_sizes; (void)out_size;
}